// round 7
// baseline (speedup 1.0000x reference)
#include <cuda_runtime.h>
#include <cuda_fp16.h>
#include <cstdint>
#include <cstddef>

#define DIM   2048
#define TDIM  6144
#define BB    2
#define TT    8192
#define MROWS (BB*TT)
#define WSZ   128
#define NBLK  (MROWS/WSZ)

// ---------------- scratch (static device globals) ----------------
__device__ __half g_xh[(size_t)MROWS * DIM];
__device__ __half g_xl[(size_t)MROWS * DIM];
__device__ __half g_wah[(size_t)TDIM * DIM];
__device__ __half g_woh[(size_t)DIM * DIM];
__device__ __half g_qkvh[(size_t)MROWS * TDIM];
__device__ __half g_qkvl[(size_t)MROWS * TDIM];
__device__ __half g_awh[(size_t)NBLK * WSZ * 256];
__device__ __half g_awl[(size_t)NBLK * WSZ * 256];
__device__ __half g_ath[(size_t)MROWS * DIM];
__device__ __half g_atl[(size_t)MROWS * DIM];

// ---------------- helpers ----------------
__device__ __forceinline__ uint32_t smem_u32(const void* p) {
    uint32_t a;
    asm("{ .reg .u64 t; cvta.to.shared.u64 t, %1; cvt.u32.u64 %0, t; }" : "=r"(a) : "l"(p));
    return a;
}
#define SWZ128(o) ((o) ^ (((o) >> 3) & 0x70))

#define LDSM_X4(r, a) \
    asm volatile("ldmatrix.sync.aligned.m8n8.x4.shared.b16 {%0,%1,%2,%3}, [%4];" \
        : "=r"((r)[0]), "=r"((r)[1]), "=r"((r)[2]), "=r"((r)[3]) : "r"(a))
#define LDSM_X4_T(r, a) \
    asm volatile("ldmatrix.sync.aligned.m8n8.x4.trans.shared.b16 {%0,%1,%2,%3}, [%4];" \
        : "=r"((r)[0]), "=r"((r)[1]), "=r"((r)[2]), "=r"((r)[3]) : "r"(a))

__device__ __forceinline__ void mma16816(float* d, const uint32_t* a, const uint32_t* b) {
    asm volatile("mma.sync.aligned.m16n8k16.row.col.f32.f16.f16.f32 "
        "{%0,%1,%2,%3}, {%4,%5,%6,%7}, {%8,%9}, {%0,%1,%2,%3};"
        : "+f"(d[0]), "+f"(d[1]), "+f"(d[2]), "+f"(d[3])
        : "r"(a[0]), "r"(a[1]), "r"(a[2]), "r"(a[3]), "r"(b[0]), "r"(b[1]));
}

#define CPA(dst, src) \
    asm volatile("cp.async.cg.shared.global [%0], [%1], 16;" :: "r"(dst), "l"(src))
#define CPA_Z(dst, src, pred) \
    asm volatile("cp.async.cg.shared.global [%0], [%1], 16, %2;" :: "r"(dst), "l"(src), "r"((pred) ? 16 : 0))
#define CP_COMMIT() asm volatile("cp.async.commit_group;" ::: "memory")
#define CP_WAIT(n)  asm volatile("cp.async.wait_group %0;" :: "n"(n) : "memory")

__device__ __forceinline__ void write_hl2(__half* H, __half* L, size_t idx, float v0, float v1) {
    __half h0 = __float2half_rn(v0), h1 = __float2half_rn(v1);
    __half l0 = __float2half_rn(v0 - __half2float(h0));
    __half l1 = __float2half_rn(v1 - __half2float(h1));
    *(__half2*)(H + idx) = __halves2half2(h0, h1);
    *(__half2*)(L + idx) = __halves2half2(l0, l1);
}

// ---------------- fp32 -> fp16 splits ----------------
__global__ __launch_bounds__(256) void split_hl_kernel(
    const float* __restrict__ src, __half* __restrict__ hi,
    __half* __restrict__ lo, int n4)
{
    int i = blockIdx.x * blockDim.x + threadIdx.x;
    if (i >= n4) return;
    float4 v = ((const float4*)src)[i];
    float vv[4] = {v.x, v.y, v.z, v.w};
    __half h4[4], l4[4];
    #pragma unroll
    for (int j = 0; j < 4; j++) {
        __half h = __float2half_rn(vv[j]);
        h4[j] = h;
        l4[j] = __float2half_rn(vv[j] - __half2float(h));
    }
    ((uint2*)hi)[i] = *(uint2*)h4;
    ((uint2*)lo)[i] = *(uint2*)l4;
}

__global__ __launch_bounds__(256) void split_h_kernel(
    const float* __restrict__ src, __half* __restrict__ hi, int n4)
{
    int i = blockIdx.x * blockDim.x + threadIdx.x;
    if (i >= n4) return;
    float4 v = ((const float4*)src)[i];
    float vv[4] = {v.x, v.y, v.z, v.w};
    __half h4[4];
    #pragma unroll
    for (int j = 0; j < 4; j++) h4[j] = __float2half_rn(vv[j]);
    ((uint2*)hi)[i] = *(uint2*)h4;
}

// ---------------- split-fp16 HMMA GEMM: C = A @ B^T ----------------
// 128x128 CTA tile, 512 threads / 16 warps, warp tile 32x32, 3-stage cp.async.
#define TILE_B   16384
#define STAGE_B  (3*TILE_B)
#define NSTG     3
#define GEMM_SMEM (NSTG*STAGE_B + 1024)

template<int OUT_HL>
__global__ __launch_bounds__(512, 1) void gemm_hmma(
    const __half* __restrict__ Ahg, const __half* __restrict__ Alg,
    const __half* __restrict__ Bhg,
    float* __restrict__ C, __half* __restrict__ Ch, __half* __restrict__ Cl,
    int M, int N, int K, int scale_cols, float scale)
{
    extern __shared__ char smem[];
    const uint32_t tiles = (smem_u32(smem) + 1023) & ~1023u;
    const int tid = threadIdx.x, wid = tid >> 5, lane = tid & 31;
    const int m0 = blockIdx.y << 7, n0 = blockIdx.x << 7;
    const int wm = (wid & 3) << 5, wn = (wid >> 2) << 5;

    const __half* Ah = Ahg + (size_t)m0 * K;
    const __half* Al = Alg + (size_t)m0 * K;
    const __half* Bh = Bhg + (size_t)n0 * K;

    float acc[2][4][4];
    #pragma unroll
    for (int a = 0; a < 2; a++)
        #pragma unroll
        for (int b = 0; b < 4; b++)
            #pragma unroll
            for (int c = 0; c < 4; c++) acc[a][b][c] = 0.f;

    const int mat = lane >> 3, lr = lane & 7;
    const int rA = ((mat & 1) << 3) + lr, cA = (mat >> 1) << 4;
    const int rB = ((mat >> 1) << 3) + lr, cB = (mat & 1) << 4;

    auto load_stage = [&](int st, int k0) {
        const uint32_t base = tiles + st * STAGE_B;
        const __half* srcs[3] = {Ah + k0, Al + k0, Bh + k0};
        #pragma unroll
        for (int t = 0; t < 3; t++) {
            const uint32_t tb = base + t * TILE_B;
            const __half* s = srcs[t];
            #pragma unroll
            for (int i = 0; i < 2; i++) {
                int idx = tid + (i << 9);
                int row = idx >> 3, c = idx & 7;
                CPA(tb + SWZ128(row * 128 + c * 16), s + (size_t)row * K + c * 8);
            }
        }
    };

    const int NS = K >> 6;
    load_stage(0, 0);
    CP_COMMIT();
    load_stage(1, 64);
    CP_COMMIT();

    int sidx = 0;
    for (int s = 0; s < NS; s++) {
        CP_WAIT(1);
        __syncthreads();
        if (s + 2 < NS) {
            int nst = sidx + 2; if (nst >= NSTG) nst -= NSTG;
            load_stage(nst, (s + 2) * 64);
            CP_COMMIT();
        }
        const uint32_t sAh = tiles + sidx * STAGE_B;
        const uint32_t sAl = sAh + TILE_B;
        const uint32_t sBh = sAh + 2 * TILE_B;

        #pragma unroll
        for (int k16 = 0; k16 < 4; k16++) {
            uint32_t ah[2][4], al[2][4], bh[4][2];
            #pragma unroll
            for (int tm = 0; tm < 2; tm++) {
                uint32_t off = SWZ128((uint32_t)((wm + tm * 16 + rA) * 128 + cA + k16 * 32));
                LDSM_X4(ah[tm], sAh + off);
                LDSM_X4(al[tm], sAl + off);
            }
            #pragma unroll
            for (int p = 0; p < 2; p++) {
                uint32_t off = SWZ128((uint32_t)((wn + p * 16 + rB) * 128 + cB + k16 * 32));
                uint32_t t[4];
                LDSM_X4(t, sBh + off);
                bh[2*p][0] = t[0]; bh[2*p][1] = t[1];
                bh[2*p+1][0] = t[2]; bh[2*p+1][1] = t[3];
            }
            #pragma unroll
            for (int tm = 0; tm < 2; tm++)
                #pragma unroll
                for (int tn = 0; tn < 4; tn++) {
                    mma16816(acc[tm][tn], ah[tm], bh[tn]);
                    mma16816(acc[tm][tn], al[tm], bh[tn]);
                }
        }
        if (++sidx == NSTG) sidx = 0;
        __syncthreads();
    }

    const int lr4 = lane >> 2, lc2 = (lane & 3) << 1;
    #pragma unroll
    for (int tm = 0; tm < 2; tm++)
        #pragma unroll
        for (int tn = 0; tn < 4; tn++) {
            int gr = m0 + wm + tm * 16 + lr4;
            int gc = n0 + wn + tn * 8 + lc2;
            float sc = (gc < scale_cols) ? scale : 1.0f;
            float v0 = acc[tm][tn][0] * sc, v1 = acc[tm][tn][1] * sc;
            float v2 = acc[tm][tn][2] * sc, v3 = acc[tm][tn][3] * sc;
            if (OUT_HL) {
                write_hl2(Ch, Cl, (size_t)gr * N + gc, v0, v1);
                write_hl2(Ch, Cl, (size_t)(gr + 8) * N + gc, v2, v3);
            } else {
                float* c0 = C + (size_t)gr * N + gc;
                c0[0] = v0; c0[1] = v1;
                float* c1 = c0 + 8 * (size_t)N;
                c1[0] = v2; c1[1] = v3;
            }
        }
}

// ---------------- attn_sim (HMMA): sim = q @ k2^T, mask, relu^2, hi/lo out ----------------
#define ASTAGE_B (4*TILE_B)
#define ASIM_SMEM (NSTG*ASTAGE_B + 1024)

__global__ __launch_bounds__(512, 1) void attn_sim_hmma(
    const __half* __restrict__ qkvh, const __half* __restrict__ qkvl,
    __half* __restrict__ awh, __half* __restrict__ awl)
{
    extern __shared__ char smem[];
    const uint32_t tiles = (smem_u32(smem) + 1023) & ~1023u;
    const int tid = threadIdx.x, wid = tid >> 5, lane = tid & 31;
    const int jhalf = blockIdx.x;
    const int blk = blockIdx.y;
    const int b = blk >> 6, wblk = blk & 63;
    const int qbase = b * TT + wblk * WSZ;
    const int krow0 = qbase - WSZ + jhalf * WSZ;
    const int bstart = b * TT;
    const int wm = (wid & 3) << 5, wn = (wid >> 2) << 5;

    float acc[2][4][4];
    #pragma unroll
    for (int a = 0; a < 2; a++)
        #pragma unroll
        for (int b2 = 0; b2 < 4; b2++)
            #pragma unroll
            for (int c = 0; c < 4; c++) acc[a][b2][c] = 0.f;

    const int mat = lane >> 3, lr = lane & 7;
    const int rA = ((mat & 1) << 3) + lr, cA = (mat >> 1) << 4;
    const int rB = ((mat >> 1) << 3) + lr, cB = (mat & 1) << 4;

    auto load_stage = [&](int st, int k0) {
        const uint32_t base = tiles + st * ASTAGE_B;
        #pragma unroll
        for (int i = 0; i < 2; i++) {
            int idx = tid + (i << 9);
            int row = idx >> 3, c = idx & 7;
            size_t qoff = (size_t)(qbase + row) * TDIM + k0 + c * 8;
            uint32_t d = SWZ128(row * 128 + c * 16);
            CPA(base + d, qkvh + qoff);
            CPA(base + TILE_B + d, qkvl + qoff);
            int grow = krow0 + row;
            bool ok = grow >= bstart;
            size_t koff = (size_t)grow * TDIM + DIM + k0 + c * 8;
            CPA_Z(base + 2 * TILE_B + d, qkvh + koff, ok);
            CPA_Z(base + 3 * TILE_B + d, qkvl + koff, ok);
        }
    };

    const int NS = DIM >> 6;
    load_stage(0, 0);
    CP_COMMIT();
    load_stage(1, 64);
    CP_COMMIT();

    int sidx = 0;
    for (int s = 0; s < NS; s++) {
        CP_WAIT(1);
        __syncthreads();
        if (s + 2 < NS) {
            int nst = sidx + 2; if (nst >= NSTG) nst -= NSTG;
            load_stage(nst, (s + 2) * 64);
            CP_COMMIT();
        }
        const uint32_t sQh = tiles + sidx * ASTAGE_B;
        const uint32_t sQl = sQh + TILE_B;
        const uint32_t sKh = sQh + 2 * TILE_B;
        const uint32_t sKl = sQh + 3 * TILE_B;

        #pragma unroll
        for (int k16 = 0; k16 < 4; k16++) {
            uint32_t ah[2][4], al[2][4], bh[4][2], bl[4][2];
            #pragma unroll
            for (int tm = 0; tm < 2; tm++) {
                uint32_t off = SWZ128((uint32_t)((wm + tm * 16 + rA) * 128 + cA + k16 * 32));
                LDSM_X4(ah[tm], sQh + off);
                LDSM_X4(al[tm], sQl + off);
            }
            #pragma unroll
            for (int p = 0; p < 2; p++) {
                uint32_t off = SWZ128((uint32_t)((wn + p * 16 + rB) * 128 + cB + k16 * 32));
                uint32_t t[4];
                LDSM_X4(t, sKh + off);
                bh[2*p][0] = t[0]; bh[2*p][1] = t[1];
                bh[2*p+1][0] = t[2]; bh[2*p+1][1] = t[3];
                LDSM_X4(t, sKl + off);
                bl[2*p][0] = t[0]; bl[2*p][1] = t[1];
                bl[2*p+1][0] = t[2]; bl[2*p+1][1] = t[3];
            }
            #pragma unroll
            for (int tm = 0; tm < 2; tm++)
                #pragma unroll
                for (int tn = 0; tn < 4; tn++) {
                    mma16816(acc[tm][tn], ah[tm], bh[tn]);
                    mma16816(acc[tm][tn], ah[tm], bl[tn]);
                    mma16816(acc[tm][tn], al[tm], bh[tn]);
                }
        }
        if (++sidx == NSTG) sidx = 0;
        __syncthreads();
    }

    const bool prevok = (wblk > 0);
    const int lr4 = lane >> 2, lc2 = (lane & 3) << 1;
    __half* oh = awh + (size_t)blk * WSZ * 256;
    __half* ol = awl + (size_t)blk * WSZ * 256;
    #pragma unroll
    for (int tm = 0; tm < 2; tm++)
        #pragma unroll
        for (int tn = 0; tn < 4; tn++) {
            #pragma unroll
            for (int half8 = 0; half8 < 2; half8++) {
                int i = wm + tm * 16 + lr4 + half8 * 8;
                int jl = wn + tn * 8 + lc2;
                int j = (jhalf << 7) + jl;
                float r[2];
                #pragma unroll
                for (int u = 0; u < 2; u++) {
                    int jj = j + u;
                    bool keep = (jj >= i) && (jj <= i + WSZ) && (prevok || jj >= WSZ);
                    float sv = acc[tm][tn][half8 * 2 + u];
                    r[u] = (keep && sv > 0.f) ? sv * sv : 0.f;
                }
                write_hl2(oh, ol, (size_t)i * 256 + j, r[0], r[1]);
            }
        }
}

// ---------------- attn_out (HMMA): out = attn @ v2, hi/lo out ----------------
#define VTILE_B  16384
#define OSTAGE_B (2*TILE_B + 2*VTILE_B)
#define AOUT_SMEM (NSTG*OSTAGE_B + 1024)
#define SWZV(off) ((off) ^ ((((off) >> 8) & 7) << 4))

__global__ __launch_bounds__(512, 1) void attn_out_hmma(
    const __half* __restrict__ qkvh, const __half* __restrict__ qkvl,
    const __half* __restrict__ awh, const __half* __restrict__ awl,
    __half* __restrict__ ath, __half* __restrict__ atl)
{
    extern __shared__ char smem[];
    const uint32_t tiles = (smem_u32(smem) + 1023) & ~1023u;
    const int tid = threadIdx.x, wid = tid >> 5, lane = tid & 31;
    const int n0 = blockIdx.x << 7;
    const int blk = blockIdx.y;
    const int b = blk >> 6, wblk = blk & 63;
    const int qbase = b * TT + wblk * WSZ;
    const int krow0 = qbase - WSZ;
    const int bstart = b * TT;
    const int wm = (wid & 3) << 5, wn = (wid >> 2) << 5;

    const __half* Ah = awh + (size_t)blk * WSZ * 256;
    const __half* Al = awl + (size_t)blk * WSZ * 256;

    float acc[2][4][4];
    #pragma unroll
    for (int a = 0; a < 2; a++)
        #pragma unroll
        for (int b2 = 0; b2 < 4; b2++)
            #pragma unroll
            for (int c = 0; c < 4; c++) acc[a][b2][c] = 0.f;

    const int mat = lane >> 3, lr = lane & 7;
    const int rA = ((mat & 1) << 3) + lr, cA = (mat >> 1) << 4;

    auto load_stage = [&](int st, int k0) {
        const uint32_t base = tiles + st * OSTAGE_B;
        #pragma unroll
        for (int i = 0; i < 2; i++) {
            int idx = tid + (i << 9);
            int row = idx >> 3, c = idx & 7;
            size_t off = (size_t)row * 256 + k0 + c * 8;
            uint32_t d = SWZ128(row * 128 + c * 16);
            CPA(base + d, Ah + off);
            CPA(base + TILE_B + d, Al + off);
        }
        #pragma unroll
        for (int i = 0; i < 2; i++) {
            int idx = tid + (i << 9);
            int j = idx >> 4, c = idx & 15;
            int grow = krow0 + k0 + j;
            bool ok = grow >= bstart;
            size_t off = (size_t)grow * TDIM + 2 * DIM + n0 + c * 8;
            uint32_t d = SWZV((uint32_t)(j * 256 + c * 16));
            CPA_Z(base + 2 * TILE_B + d, qkvh + off, ok);
            CPA_Z(base + 2 * TILE_B + VTILE_B + d, qkvl + off, ok);
        }
    };

    const int NS = 4;
    load_stage(0, 0);
    CP_COMMIT();
    load_stage(1, 64);
    CP_COMMIT();

    int sidx = 0;
    for (int s = 0; s < NS; s++) {
        CP_WAIT(1);
        __syncthreads();
        if (s + 2 < NS) {
            int nst = sidx + 2; if (nst >= NSTG) nst -= NSTG;
            load_stage(nst, (s + 2) * 64);
            CP_COMMIT();
        }
        const uint32_t sAh = tiles + sidx * OSTAGE_B;
        const uint32_t sAl = sAh + TILE_B;
        const uint32_t sVh = sAh + 2 * TILE_B;
        const uint32_t sVl = sVh + VTILE_B;

        #pragma unroll
        for (int k16 = 0; k16 < 4; k16++) {
            uint32_t ah[2][4], al[2][4], bh[4][2], bl[4][2];
            #pragma unroll
            for (int tm = 0; tm < 2; tm++) {
                uint32_t off = SWZ128((uint32_t)((wm + tm * 16 + rA) * 128 + cA + k16 * 32));
                LDSM_X4(ah[tm], sAh + off);
                LDSM_X4(al[tm], sAl + off);
            }
            #pragma unroll
            for (int p = 0; p < 2; p++) {
                int nn = wn + p * 16;
                uint32_t off = SWZV((uint32_t)((k16 * 16 + (lane & 15)) * 256 + (nn + ((lane >> 4) << 3)) * 2));
                uint32_t t[4];
                LDSM_X4_T(t, sVh + off);
                bh[2*p][0] = t[0]; bh[2*p][1] = t[1];
                bh[2*p+1][0] = t[2]; bh[2*p+1][1] = t[3];
                LDSM_X4_T(t, sVl + off);
                bl[2*p][0] = t[0]; bl[2*p][1] = t[1];
                bl[2*p+1][0] = t[2]; bl[2*p+1][1] = t[3];
            }
            #pragma unroll
            for (int tm = 0; tm < 2; tm++)
                #pragma unroll
                for (int tn = 0; tn < 4; tn++) {
                    mma16816(acc[tm][tn], ah[tm], bh[tn]);
                    mma16816(acc[tm][tn], ah[tm], bl[tn]);
                    mma16816(acc[tm][tn], al[tm], bh[tn]);
                }
        }
        if (++sidx == NSTG) sidx = 0;
        __syncthreads();
    }

    const int lr4 = lane >> 2, lc2 = (lane & 3) << 1;
    #pragma unroll
    for (int tm = 0; tm < 2; tm++)
        #pragma unroll
        for (int tn = 0; tn < 4; tn++) {
            int gr = qbase + wm + tm * 16 + lr4;
            int gc = n0 + wn + tn * 8 + lc2;
            write_hl2(ath, atl, (size_t)gr * DIM + gc, acc[tm][tn][0], acc[tm][tn][1]);
            write_hl2(ath, atl, (size_t)(gr + 8) * DIM + gc, acc[tm][tn][2], acc[tm][tn][3]);
        }
}

// ---------------------------------------------------------------------------
extern "C" void kernel_launch(void* const* d_in, const int* in_sizes, int n_in,
                              void* d_out, int out_size)
{
    (void)in_sizes; (void)n_in; (void)out_size;
    const float* x      = (const float*)d_in[0];
    const float* w_attn = (const float*)d_in[1];
    const float* w_o    = (const float*)d_in[2];
    float* out = (float*)d_out;

    __half *xh, *xl, *wah, *woh, *qkvh, *qkvl, *awh, *awl, *ath, *atl;
    cudaGetSymbolAddress((void**)&xh,   g_xh);   cudaGetSymbolAddress((void**)&xl,   g_xl);
    cudaGetSymbolAddress((void**)&wah,  g_wah);  cudaGetSymbolAddress((void**)&woh,  g_woh);
    cudaGetSymbolAddress((void**)&qkvh, g_qkvh); cudaGetSymbolAddress((void**)&qkvl, g_qkvl);
    cudaGetSymbolAddress((void**)&awh,  g_awh);  cudaGetSymbolAddress((void**)&awl,  g_awl);
    cudaGetSymbolAddress((void**)&ath,  g_ath);  cudaGetSymbolAddress((void**)&atl,  g_atl);

    cudaFuncSetAttribute(gemm_hmma<0>, cudaFuncAttributeMaxDynamicSharedMemorySize, GEMM_SMEM);
    cudaFuncSetAttribute(gemm_hmma<1>, cudaFuncAttributeMaxDynamicSharedMemorySize, GEMM_SMEM);
    cudaFuncSetAttribute(attn_sim_hmma, cudaFuncAttributeMaxDynamicSharedMemorySize, ASIM_SMEM);
    cudaFuncSetAttribute(attn_out_hmma, cudaFuncAttributeMaxDynamicSharedMemorySize, AOUT_SMEM);

    // 0) fp16 splits
    {
        int n4 = MROWS * DIM / 4;
        split_hl_kernel<<<(n4 + 255) / 256, 256>>>(x, xh, xl, n4);
        n4 = TDIM * DIM / 4;
        split_h_kernel<<<(n4 + 255) / 256, 256>>>(w_attn, wah, n4);
        n4 = DIM * DIM / 4;
        split_h_kernel<<<(n4 + 255) / 256, 256>>>(w_o, woh, n4);
    }

    // 1) qkv = x @ w_attn^T -> hi/lo fp16  (q cols scaled by 1/W)
    gemm_hmma<1><<<dim3(TDIM / 128, MROWS / 128), 512, GEMM_SMEM>>>(
        xh, xl, wah, nullptr, qkvh, qkvl, MROWS, TDIM, DIM, DIM, 1.0f / (float)WSZ);

    // 2) attention weights (HMMA) -> hi/lo fp16
    attn_sim_hmma<<<dim3(2, NBLK), 512, ASIM_SMEM>>>(qkvh, qkvl, awh, awl);

    // 3) attn @ v (HMMA) -> hi/lo fp16
    attn_out_hmma<<<dim3(DIM / 128, NBLK), 512, AOUT_SMEM>>>(
        qkvh, qkvl, awh, awl, ath, atl);

    // 4) out = att @ w_o^T -> fp32
    gemm_hmma<0><<<dim3(DIM / 128, MROWS / 128), 512, GEMM_SMEM>>>(
        ath, atl, woh, out, nullptr, nullptr, MROWS, DIM, DIM, 0, 1.0f);
}

// round 9
// speedup vs baseline: 1.0904x; 1.0904x over previous
#include <cuda_runtime.h>
#include <cuda_fp16.h>
#include <cstdint>
#include <cstddef>

#define DIM   2048
#define TDIM  6144
#define BB    2
#define TT    8192
#define MROWS (BB*TT)
#define WSZ   128
#define NBLK  (MROWS/WSZ)

// ---------------- scratch (static device globals) ----------------
__device__ __half g_xh[(size_t)MROWS * DIM];
__device__ __half g_xl[(size_t)MROWS * DIM];
__device__ __half g_wah[(size_t)TDIM * DIM];
__device__ __half g_woh[(size_t)DIM * DIM];
__device__ __half g_qkvh[(size_t)MROWS * TDIM];
__device__ __half g_qkvl[(size_t)MROWS * TDIM];
__device__ __half g_awh[(size_t)NBLK * WSZ * 256];
__device__ __half g_awl[(size_t)NBLK * WSZ * 256];
__device__ __half g_ath[(size_t)MROWS * DIM];
__device__ __half g_atl[(size_t)MROWS * DIM];

// ---------------- helpers ----------------
__device__ __forceinline__ uint32_t smem_u32(const void* p) {
    uint32_t a;
    asm("{ .reg .u64 t; cvta.to.shared.u64 t, %1; cvt.u32.u64 %0, t; }" : "=r"(a) : "l"(p));
    return a;
}
#define SWZ128(o) ((o) ^ (((o) >> 3) & 0x70))

#define LDSM_X4(r, a) \
    asm volatile("ldmatrix.sync.aligned.m8n8.x4.shared.b16 {%0,%1,%2,%3}, [%4];" \
        : "=r"((r)[0]), "=r"((r)[1]), "=r"((r)[2]), "=r"((r)[3]) : "r"(a))
#define LDSM_X4_T(r, a) \
    asm volatile("ldmatrix.sync.aligned.m8n8.x4.trans.shared.b16 {%0,%1,%2,%3}, [%4];" \
        : "=r"((r)[0]), "=r"((r)[1]), "=r"((r)[2]), "=r"((r)[3]) : "r"(a))

__device__ __forceinline__ void mma16816(float* d, const uint32_t* a, const uint32_t* b) {
    asm volatile("mma.sync.aligned.m16n8k16.row.col.f32.f16.f16.f32 "
        "{%0,%1,%2,%3}, {%4,%5,%6,%7}, {%8,%9}, {%0,%1,%2,%3};"
        : "+f"(d[0]), "+f"(d[1]), "+f"(d[2]), "+f"(d[3])
        : "r"(a[0]), "r"(a[1]), "r"(a[2]), "r"(a[3]), "r"(b[0]), "r"(b[1]));
}

#define CPA(dst, src) \
    asm volatile("cp.async.cg.shared.global [%0], [%1], 16;" :: "r"(dst), "l"(src))
#define CPA_Z(dst, src, pred) \
    asm volatile("cp.async.cg.shared.global [%0], [%1], 16, %2;" :: "r"(dst), "l"(src), "r"((pred) ? 16 : 0))
#define CP_COMMIT() asm volatile("cp.async.commit_group;" ::: "memory")
#define CP_WAIT(n)  asm volatile("cp.async.wait_group %0;" :: "n"(n) : "memory")

__device__ __forceinline__ void write_hl2(__half* H, __half* L, size_t idx, float v0, float v1) {
    __half h0 = __float2half_rn(v0), h1 = __float2half_rn(v1);
    __half l0 = __float2half_rn(v0 - __half2float(h0));
    __half l1 = __float2half_rn(v1 - __half2float(h1));
    *(__half2*)(H + idx) = __halves2half2(h0, h1);
    *(__half2*)(L + idx) = __halves2half2(l0, l1);
}

// ---------------- fp32 -> fp16 splits ----------------
__global__ __launch_bounds__(256) void split_hl_kernel(
    const float* __restrict__ src, __half* __restrict__ hi,
    __half* __restrict__ lo, int n4)
{
    int i = blockIdx.x * blockDim.x + threadIdx.x;
    if (i >= n4) return;
    float4 v = ((const float4*)src)[i];
    float vv[4] = {v.x, v.y, v.z, v.w};
    __half h4[4], l4[4];
    #pragma unroll
    for (int j = 0; j < 4; j++) {
        __half h = __float2half_rn(vv[j]);
        h4[j] = h;
        l4[j] = __float2half_rn(vv[j] - __half2float(h));
    }
    ((uint2*)hi)[i] = *(uint2*)h4;
    ((uint2*)lo)[i] = *(uint2*)l4;
}

__global__ __launch_bounds__(256) void split_h_kernel(
    const float* __restrict__ src, __half* __restrict__ hi, int n4)
{
    int i = blockIdx.x * blockDim.x + threadIdx.x;
    if (i >= n4) return;
    float4 v = ((const float4*)src)[i];
    float vv[4] = {v.x, v.y, v.z, v.w};
    __half h4[4];
    #pragma unroll
    for (int j = 0; j < 4; j++) h4[j] = __float2half_rn(vv[j]);
    ((uint2*)hi)[i] = *(uint2*)h4;
}

// ---------------- split-fp16 HMMA GEMM: C = A @ B^T ----------------
// 128x256 CTA tile, 256 threads / 8 warps, warp tile 64x64, 3-stage cp.async.
#define TILE_B   16384               // 128 rows x 128 bytes
#define GTILE_BB 32768               // 256 rows x 128 bytes (B tile)
#define GSTAGE_B (2*TILE_B + GTILE_BB)
#define NSTG     3
#define GEMM_SMEM (NSTG*GSTAGE_B + 1024)

template<int OUT_HL>
__global__ __launch_bounds__(256, 1) void gemm_hmma(
    const __half* __restrict__ Ahg, const __half* __restrict__ Alg,
    const __half* __restrict__ Bhg,
    float* __restrict__ C, __half* __restrict__ Ch, __half* __restrict__ Cl,
    int M, int N, int K, int scale_cols, float scale)
{
    extern __shared__ char smem[];
    const uint32_t tiles = (smem_u32(smem) + 1023) & ~1023u;
    const int tid = threadIdx.x, wid = tid >> 5, lane = tid & 31;
    const int m0 = blockIdx.y << 7, n0 = blockIdx.x << 8;
    const int wm = (wid & 1) << 6, wn = (wid >> 1) << 6;

    const __half* Ah = Ahg + (size_t)m0 * K;
    const __half* Al = Alg + (size_t)m0 * K;
    const __half* Bh = Bhg + (size_t)n0 * K;

    float acc[4][8][4];
    #pragma unroll
    for (int a = 0; a < 4; a++)
        #pragma unroll
        for (int b = 0; b < 8; b++)
            #pragma unroll
            for (int c = 0; c < 4; c++) acc[a][b][c] = 0.f;

    const int mat = lane >> 3, lr = lane & 7;
    const int rA = ((mat & 1) << 3) + lr, cA = (mat >> 1) << 4;
    const int rB = ((mat >> 1) << 3) + lr, cB = (mat & 1) << 4;

    auto load_stage = [&](int st, int k0) {
        const uint32_t base = tiles + st * GSTAGE_B;
        // A hi/lo: 128 rows x 128B each
        #pragma unroll
        for (int i = 0; i < 4; i++) {
            int idx = tid + (i << 8);
            int row = idx >> 3, c = idx & 7;
            uint32_t d = SWZ128(row * 128 + c * 16);
            CPA(base + d, Ah + (size_t)row * K + k0 + c * 8);
            CPA(base + TILE_B + d, Al + (size_t)row * K + k0 + c * 8);
        }
        // B hi: 256 rows x 128B
        #pragma unroll
        for (int i = 0; i < 8; i++) {
            int idx = tid + (i << 8);
            int row = idx >> 3, c = idx & 7;
            CPA(base + 2 * TILE_B + SWZ128(row * 128 + c * 16),
                Bh + (size_t)row * K + k0 + c * 8);
        }
    };

    const int NS = K >> 6;
    load_stage(0, 0);
    CP_COMMIT();
    load_stage(1, 64);
    CP_COMMIT();

    int sidx = 0;
    for (int s = 0; s < NS; s++) {
        CP_WAIT(1);
        __syncthreads();
        if (s + 2 < NS) {
            int nst = sidx + 2; if (nst >= NSTG) nst -= NSTG;
            load_stage(nst, (s + 2) * 64);
            CP_COMMIT();
        }
        const uint32_t sAh = tiles + sidx * GSTAGE_B;
        const uint32_t sAl = sAh + TILE_B;
        const uint32_t sBh = sAh + 2 * TILE_B;

        #pragma unroll
        for (int k16 = 0; k16 < 4; k16++) {
            uint32_t ah[4][4], al[4][4], bh[8][2];
            #pragma unroll
            for (int tm = 0; tm < 4; tm++) {
                uint32_t off = SWZ128((uint32_t)((wm + tm * 16 + rA) * 128 + cA + k16 * 32));
                LDSM_X4(ah[tm], sAh + off);
                LDSM_X4(al[tm], sAl + off);
            }
            #pragma unroll
            for (int p = 0; p < 4; p++) {
                uint32_t off = SWZ128((uint32_t)((wn + p * 16 + rB) * 128 + cB + k16 * 32));
                uint32_t t[4];
                LDSM_X4(t, sBh + off);
                bh[2*p][0] = t[0]; bh[2*p][1] = t[1];
                bh[2*p+1][0] = t[2]; bh[2*p+1][1] = t[3];
            }
            #pragma unroll
            for (int tm = 0; tm < 4; tm++)
                #pragma unroll
                for (int tn = 0; tn < 8; tn++) {
                    mma16816(acc[tm][tn], ah[tm], bh[tn]);
                    mma16816(acc[tm][tn], al[tm], bh[tn]);
                }
        }
        if (++sidx == NSTG) sidx = 0;
        __syncthreads();
    }

    const int lr4 = lane >> 2, lc2 = (lane & 3) << 1;
    #pragma unroll
    for (int tm = 0; tm < 4; tm++)
        #pragma unroll
        for (int tn = 0; tn < 8; tn++) {
            int gr = m0 + wm + tm * 16 + lr4;
            int gc = n0 + wn + tn * 8 + lc2;
            float sc = (gc < scale_cols) ? scale : 1.0f;
            float v0 = acc[tm][tn][0] * sc, v1 = acc[tm][tn][1] * sc;
            float v2 = acc[tm][tn][2] * sc, v3 = acc[tm][tn][3] * sc;
            if (OUT_HL) {
                write_hl2(Ch, Cl, (size_t)gr * N + gc, v0, v1);
                write_hl2(Ch, Cl, (size_t)(gr + 8) * N + gc, v2, v3);
            } else {
                float* c0 = C + (size_t)gr * N + gc;
                c0[0] = v0; c0[1] = v1;
                float* c1 = c0 + 8 * (size_t)N;
                c1[0] = v2; c1[1] = v3;
            }
        }
}

// ---------------- attn_sim (HMMA): sim = q @ k2^T, mask, relu^2, hi/lo out ----------------
#define ASTAGE_B (4*TILE_B)
#define ASIM_SMEM (NSTG*ASTAGE_B + 1024)

__global__ __launch_bounds__(256, 1) void attn_sim_hmma(
    const __half* __restrict__ qkvh, const __half* __restrict__ qkvl,
    __half* __restrict__ awh, __half* __restrict__ awl)
{
    extern __shared__ char smem[];
    const uint32_t tiles = (smem_u32(smem) + 1023) & ~1023u;
    const int tid = threadIdx.x, wid = tid >> 5, lane = tid & 31;
    const int jhalf = blockIdx.x;
    const int blk = blockIdx.y;
    const int b = blk >> 6, wblk = blk & 63;
    const int qbase = b * TT + wblk * WSZ;
    const int krow0 = qbase - WSZ + jhalf * WSZ;
    const int bstart = b * TT;
    const int wm = (wid & 1) << 6, wn = (wid >> 1) << 5;

    float acc[4][4][4];
    #pragma unroll
    for (int a = 0; a < 4; a++)
        #pragma unroll
        for (int b2 = 0; b2 < 4; b2++)
            #pragma unroll
            for (int c = 0; c < 4; c++) acc[a][b2][c] = 0.f;

    const int mat = lane >> 3, lr = lane & 7;
    const int rA = ((mat & 1) << 3) + lr, cA = (mat >> 1) << 4;
    const int rB = ((mat >> 1) << 3) + lr, cB = (mat & 1) << 4;

    auto load_stage = [&](int st, int k0) {
        const uint32_t base = tiles + st * ASTAGE_B;
        #pragma unroll
        for (int i = 0; i < 4; i++) {
            int idx = tid + (i << 8);
            int row = idx >> 3, c = idx & 7;
            size_t qoff = (size_t)(qbase + row) * TDIM + k0 + c * 8;
            uint32_t d = SWZ128(row * 128 + c * 16);
            CPA(base + d, qkvh + qoff);
            CPA(base + TILE_B + d, qkvl + qoff);
            int grow = krow0 + row;
            bool ok = grow >= bstart;
            size_t koff = (size_t)grow * TDIM + DIM + k0 + c * 8;
            CPA_Z(base + 2 * TILE_B + d, qkvh + koff, ok);
            CPA_Z(base + 3 * TILE_B + d, qkvl + koff, ok);
        }
    };

    const int NS = DIM >> 6;
    load_stage(0, 0);
    CP_COMMIT();
    load_stage(1, 64);
    CP_COMMIT();

    int sidx = 0;
    for (int s = 0; s < NS; s++) {
        CP_WAIT(1);
        __syncthreads();
        if (s + 2 < NS) {
            int nst = sidx + 2; if (nst >= NSTG) nst -= NSTG;
            load_stage(nst, (s + 2) * 64);
            CP_COMMIT();
        }
        const uint32_t sQh = tiles + sidx * ASTAGE_B;
        const uint32_t sQl = sQh + TILE_B;
        const uint32_t sKh = sQh + 2 * TILE_B;
        const uint32_t sKl = sQh + 3 * TILE_B;

        #pragma unroll
        for (int k16 = 0; k16 < 4; k16++) {
            uint32_t ah[4][4], al[4][4], bh[4][2], bl[4][2];
            #pragma unroll
            for (int tm = 0; tm < 4; tm++) {
                uint32_t off = SWZ128((uint32_t)((wm + tm * 16 + rA) * 128 + cA + k16 * 32));
                LDSM_X4(ah[tm], sQh + off);
                LDSM_X4(al[tm], sQl + off);
            }
            #pragma unroll
            for (int p = 0; p < 2; p++) {
                uint32_t off = SWZ128((uint32_t)((wn + p * 16 + rB) * 128 + cB + k16 * 32));
                uint32_t t[4];
                LDSM_X4(t, sKh + off);
                bh[2*p][0] = t[0]; bh[2*p][1] = t[1];
                bh[2*p+1][0] = t[2]; bh[2*p+1][1] = t[3];
                LDSM_X4(t, sKl + off);
                bl[2*p][0] = t[0]; bl[2*p][1] = t[1];
                bl[2*p+1][0] = t[2]; bl[2*p+1][1] = t[3];
            }
            #pragma unroll
            for (int tm = 0; tm < 4; tm++)
                #pragma unroll
                for (int tn = 0; tn < 4; tn++) {
                    mma16816(acc[tm][tn], ah[tm], bh[tn]);
                    mma16816(acc[tm][tn], ah[tm], bl[tn]);
                    mma16816(acc[tm][tn], al[tm], bh[tn]);
                }
        }
        if (++sidx == NSTG) sidx = 0;
        __syncthreads();
    }

    const bool prevok = (wblk > 0);
    const int lr4 = lane >> 2, lc2 = (lane & 3) << 1;
    __half* oh = awh + (size_t)blk * WSZ * 256;
    __half* ol = awl + (size_t)blk * WSZ * 256;
    #pragma unroll
    for (int tm = 0; tm < 4; tm++)
        #pragma unroll
        for (int tn = 0; tn < 4; tn++) {
            #pragma unroll
            for (int half8 = 0; half8 < 2; half8++) {
                int i = wm + tm * 16 + lr4 + half8 * 8;
                int jl = wn + tn * 8 + lc2;
                int j = (jhalf << 7) + jl;
                float r[2];
                #pragma unroll
                for (int u = 0; u < 2; u++) {
                    int jj = j + u;
                    bool keep = (jj >= i) && (jj <= i + WSZ) && (prevok || jj >= WSZ);
                    float sv = acc[tm][tn][half8 * 2 + u];
                    r[u] = (keep && sv > 0.f) ? sv * sv : 0.f;
                }
                write_hl2(oh, ol, (size_t)i * 256 + j, r[0], r[1]);
            }
        }
}

// ---------------- attn_out (HMMA): out = attn @ v2, hi/lo out ----------------
#define VTILE_B  16384
#define OSTAGE_B (2*TILE_B + 2*VTILE_B)
#define AOUT_SMEM (NSTG*OSTAGE_B + 1024)
#define SWZV(off) ((off) ^ ((((off) >> 8) & 7) << 4))

__global__ __launch_bounds__(256, 1) void attn_out_hmma(
    const __half* __restrict__ qkvh, const __half* __restrict__ qkvl,
    const __half* __restrict__ awh, const __half* __restrict__ awl,
    __half* __restrict__ ath, __half* __restrict__ atl)
{
    extern __shared__ char smem[];
    const uint32_t tiles = (smem_u32(smem) + 1023) & ~1023u;
    const int tid = threadIdx.x, wid = tid >> 5, lane = tid & 31;
    const int n0 = blockIdx.x << 7;
    const int blk = blockIdx.y;
    const int b = blk >> 6, wblk = blk & 63;
    const int qbase = b * TT + wblk * WSZ;
    const int krow0 = qbase - WSZ;
    const int bstart = b * TT;
    const int wm = (wid & 1) << 6, wn = (wid >> 1) << 5;

    const __half* Ah = awh + (size_t)blk * WSZ * 256;
    const __half* Al = awl + (size_t)blk * WSZ * 256;

    float acc[4][4][4];
    #pragma unroll
    for (int a = 0; a < 4; a++)
        #pragma unroll
        for (int b2 = 0; b2 < 4; b2++)
            #pragma unroll
            for (int c = 0; c < 4; c++) acc[a][b2][c] = 0.f;

    const int mat = lane >> 3, lr = lane & 7;
    const int rA = ((mat & 1) << 3) + lr, cA = (mat >> 1) << 4;

    auto load_stage = [&](int st, int k0) {
        const uint32_t base = tiles + st * OSTAGE_B;
        #pragma unroll
        for (int i = 0; i < 4; i++) {
            int idx = tid + (i << 8);
            int row = idx >> 3, c = idx & 7;
            size_t off = (size_t)row * 256 + k0 + c * 8;
            uint32_t d = SWZ128(row * 128 + c * 16);
            CPA(base + d, Ah + off);
            CPA(base + TILE_B + d, Al + off);
        }
        #pragma unroll
        for (int i = 0; i < 4; i++) {
            int idx = tid + (i << 8);
            int j = idx >> 4, c = idx & 15;
            int grow = krow0 + k0 + j;
            bool ok = grow >= bstart;
            size_t off = (size_t)grow * TDIM + 2 * DIM + n0 + c * 8;
            uint32_t d = SWZV((uint32_t)(j * 256 + c * 16));
            CPA_Z(base + 2 * TILE_B + d, qkvh + off, ok);
            CPA_Z(base + 2 * TILE_B + VTILE_B + d, qkvl + off, ok);
        }
    };

    const int NS = 4;
    load_stage(0, 0);
    CP_COMMIT();
    load_stage(1, 64);
    CP_COMMIT();

    int sidx = 0;
    for (int s = 0; s < NS; s++) {
        CP_WAIT(1);
        __syncthreads();
        if (s + 2 < NS) {
            int nst = sidx + 2; if (nst >= NSTG) nst -= NSTG;
            load_stage(nst, (s + 2) * 64);
            CP_COMMIT();
        }
        const uint32_t sAh = tiles + sidx * OSTAGE_B;
        const uint32_t sAl = sAh + TILE_B;
        const uint32_t sVh = sAh + 2 * TILE_B;
        const uint32_t sVl = sVh + VTILE_B;

        #pragma unroll
        for (int k16 = 0; k16 < 4; k16++) {
            uint32_t ah[4][4], al[4][4], bh[4][2], bl[4][2];
            #pragma unroll
            for (int tm = 0; tm < 4; tm++) {
                uint32_t off = SWZ128((uint32_t)((wm + tm * 16 + rA) * 128 + cA + k16 * 32));
                LDSM_X4(ah[tm], sAh + off);
                LDSM_X4(al[tm], sAl + off);
            }
            #pragma unroll
            for (int p = 0; p < 2; p++) {
                int nn = wn + p * 16;
                uint32_t off = SWZV((uint32_t)((k16 * 16 + (lane & 15)) * 256 + (nn + ((lane >> 4) << 3)) * 2));
                uint32_t t[4];
                LDSM_X4_T(t, sVh + off);
                bh[2*p][0] = t[0]; bh[2*p][1] = t[1];
                bh[2*p+1][0] = t[2]; bh[2*p+1][1] = t[3];
                LDSM_X4_T(t, sVl + off);
                bl[2*p][0] = t[0]; bl[2*p][1] = t[1];
                bl[2*p+1][0] = t[2]; bl[2*p+1][1] = t[3];
            }
            #pragma unroll
            for (int tm = 0; tm < 4; tm++)
                #pragma unroll
                for (int tn = 0; tn < 4; tn++) {
                    mma16816(acc[tm][tn], ah[tm], bh[tn]);
                    mma16816(acc[tm][tn], ah[tm], bl[tn]);
                    mma16816(acc[tm][tn], al[tm], bh[tn]);
                }
        }
        if (++sidx == NSTG) sidx = 0;
        __syncthreads();
    }

    const int lr4 = lane >> 2, lc2 = (lane & 3) << 1;
    #pragma unroll
    for (int tm = 0; tm < 4; tm++)
        #pragma unroll
        for (int tn = 0; tn < 4; tn++) {
            int gr = qbase + wm + tm * 16 + lr4;
            int gc = n0 + wn + tn * 8 + lc2;
            write_hl2(ath, atl, (size_t)gr * DIM + gc, acc[tm][tn][0], acc[tm][tn][1]);
            write_hl2(ath, atl, (size_t)(gr + 8) * DIM + gc, acc[tm][tn][2], acc[tm][tn][3]);
        }
}

// ---------------------------------------------------------------------------
extern "C" void kernel_launch(void* const* d_in, const int* in_sizes, int n_in,
                              void* d_out, int out_size)
{
    (void)in_sizes; (void)n_in; (void)out_size;
    const float* x      = (const float*)d_in[0];
    const float* w_attn = (const float*)d_in[1];
    const float* w_o    = (const float*)d_in[2];
    float* out = (float*)d_out;

    __half *xh, *xl, *wah, *woh, *qkvh, *qkvl, *awh, *awl, *ath, *atl;
    cudaGetSymbolAddress((void**)&xh,   g_xh);   cudaGetSymbolAddress((void**)&xl,   g_xl);
    cudaGetSymbolAddress((void**)&wah,  g_wah);  cudaGetSymbolAddress((void**)&woh,  g_woh);
    cudaGetSymbolAddress((void**)&qkvh, g_qkvh); cudaGetSymbolAddress((void**)&qkvl, g_qkvl);
    cudaGetSymbolAddress((void**)&awh,  g_awh);  cudaGetSymbolAddress((void**)&awl,  g_awl);
    cudaGetSymbolAddress((void**)&ath,  g_ath);  cudaGetSymbolAddress((void**)&atl,  g_atl);

    cudaFuncSetAttribute(gemm_hmma<0>, cudaFuncAttributeMaxDynamicSharedMemorySize, GEMM_SMEM);
    cudaFuncSetAttribute(gemm_hmma<1>, cudaFuncAttributeMaxDynamicSharedMemorySize, GEMM_SMEM);
    cudaFuncSetAttribute(attn_sim_hmma, cudaFuncAttributeMaxDynamicSharedMemorySize, ASIM_SMEM);
    cudaFuncSetAttribute(attn_out_hmma, cudaFuncAttributeMaxDynamicSharedMemorySize, AOUT_SMEM);

    // 0) fp16 splits
    {
        int n4 = MROWS * DIM / 4;
        split_hl_kernel<<<(n4 + 255) / 256, 256>>>(x, xh, xl, n4);
        n4 = TDIM * DIM / 4;
        split_h_kernel<<<(n4 + 255) / 256, 256>>>(w_attn, wah, n4);
        n4 = DIM * DIM / 4;
        split_h_kernel<<<(n4 + 255) / 256, 256>>>(w_o, woh, n4);
    }

    // 1) qkv = x @ w_attn^T -> hi/lo fp16  (q cols scaled by 1/W)
    gemm_hmma<1><<<dim3(TDIM / 256, MROWS / 128), 256, GEMM_SMEM>>>(
        xh, xl, wah, nullptr, qkvh, qkvl, MROWS, TDIM, DIM, DIM, 1.0f / (float)WSZ);

    // 2) attention weights (HMMA) -> hi/lo fp16
    attn_sim_hmma<<<dim3(2, NBLK), 256, ASIM_SMEM>>>(qkvh, qkvl, awh, awl);

    // 3) attn @ v (HMMA) -> hi/lo fp16
    attn_out_hmma<<<dim3(DIM / 128, NBLK), 256, AOUT_SMEM>>>(
        qkvh, qkvl, awh, awl, ath, atl);

    // 4) out = att @ w_o^T -> fp32
    gemm_hmma<0><<<dim3(DIM / 256, MROWS / 128), 256, GEMM_SMEM>>>(
        ath, atl, woh, out, nullptr, nullptr, MROWS, DIM, DIM, 0, 1.0f);
}

// round 10
// speedup vs baseline: 1.2361x; 1.1337x over previous
#include <cuda_runtime.h>
#include <cuda_fp16.h>
#include <cstdint>
#include <cstddef>

#define DIM   2048
#define TDIM  6144
#define BB    2
#define TT    8192
#define MROWS (BB*TT)
#define WSZ   128
#define NBLK  (MROWS/WSZ)

// ---------------- scratch (static device globals) ----------------
__device__ __half g_xh[(size_t)MROWS * DIM];
__device__ __half g_xl[(size_t)MROWS * DIM];
__device__ __half g_wah[(size_t)TDIM * DIM];
__device__ __half g_woh[(size_t)DIM * DIM];
__device__ __half g_qkvh[(size_t)MROWS * TDIM];
__device__ __half g_qkvl[(size_t)MROWS * TDIM];
__device__ __half g_awh[(size_t)NBLK * WSZ * 256];
__device__ __half g_ath[(size_t)MROWS * DIM];

// ---------------- helpers ----------------
__device__ __forceinline__ uint32_t smem_u32(const void* p) {
    uint32_t a;
    asm("{ .reg .u64 t; cvta.to.shared.u64 t, %1; cvt.u32.u64 %0, t; }" : "=r"(a) : "l"(p));
    return a;
}
#define SWZ128(o) ((o) ^ (((o) >> 3) & 0x70))

#define LDSM_X4(r, a) \
    asm volatile("ldmatrix.sync.aligned.m8n8.x4.shared.b16 {%0,%1,%2,%3}, [%4];" \
        : "=r"((r)[0]), "=r"((r)[1]), "=r"((r)[2]), "=r"((r)[3]) : "r"(a))
#define LDSM_X4_T(r, a) \
    asm volatile("ldmatrix.sync.aligned.m8n8.x4.trans.shared.b16 {%0,%1,%2,%3}, [%4];" \
        : "=r"((r)[0]), "=r"((r)[1]), "=r"((r)[2]), "=r"((r)[3]) : "r"(a))

__device__ __forceinline__ void mma16816(float* d, const uint32_t* a, const uint32_t* b) {
    asm volatile("mma.sync.aligned.m16n8k16.row.col.f32.f16.f16.f32 "
        "{%0,%1,%2,%3}, {%4,%5,%6,%7}, {%8,%9}, {%0,%1,%2,%3};"
        : "+f"(d[0]), "+f"(d[1]), "+f"(d[2]), "+f"(d[3])
        : "r"(a[0]), "r"(a[1]), "r"(a[2]), "r"(a[3]), "r"(b[0]), "r"(b[1]));
}

#define CPA(dst, src) \
    asm volatile("cp.async.cg.shared.global [%0], [%1], 16;" :: "r"(dst), "l"(src))
#define CPA_Z(dst, src, pred) \
    asm volatile("cp.async.cg.shared.global [%0], [%1], 16, %2;" :: "r"(dst), "l"(src), "r"((pred) ? 16 : 0))
#define CP_COMMIT() asm volatile("cp.async.commit_group;" ::: "memory")
#define CP_WAIT(n)  asm volatile("cp.async.wait_group %0;" :: "n"(n) : "memory")

__device__ __forceinline__ void write_hl2(__half* H, __half* L, size_t idx, float v0, float v1) {
    __half h0 = __float2half_rn(v0), h1 = __float2half_rn(v1);
    __half l0 = __float2half_rn(v0 - __half2float(h0));
    __half l1 = __float2half_rn(v1 - __half2float(h1));
    *(__half2*)(H + idx) = __halves2half2(h0, h1);
    *(__half2*)(L + idx) = __halves2half2(l0, l1);
}
__device__ __forceinline__ void write_h2(__half* H, size_t idx, float v0, float v1) {
    *(__half2*)(H + idx) = __halves2half2(__float2half_rn(v0), __float2half_rn(v1));
}

// ---------------- fp32 -> fp16 splits ----------------
__global__ __launch_bounds__(256) void split_hl_kernel(
    const float* __restrict__ src, __half* __restrict__ hi,
    __half* __restrict__ lo, int n4)
{
    int i = blockIdx.x * blockDim.x + threadIdx.x;
    if (i >= n4) return;
    float4 v = ((const float4*)src)[i];
    float vv[4] = {v.x, v.y, v.z, v.w};
    __half h4[4], l4[4];
    #pragma unroll
    for (int j = 0; j < 4; j++) {
        __half h = __float2half_rn(vv[j]);
        h4[j] = h;
        l4[j] = __float2half_rn(vv[j] - __half2float(h));
    }
    ((uint2*)hi)[i] = *(uint2*)h4;
    ((uint2*)lo)[i] = *(uint2*)l4;
}

__global__ __launch_bounds__(256) void split_h_kernel(
    const float* __restrict__ src, __half* __restrict__ hi, int n4)
{
    int i = blockIdx.x * blockDim.x + threadIdx.x;
    if (i >= n4) return;
    float4 v = ((const float4*)src)[i];
    float vv[4] = {v.x, v.y, v.z, v.w};
    __half h4[4];
    #pragma unroll
    for (int j = 0; j < 4; j++) h4[j] = __float2half_rn(vv[j]);
    ((uint2*)hi)[i] = *(uint2*)h4;
}

// ---------------- split-fp16 HMMA GEMM: C = A @ B^T ----------------
// 128x256 CTA tile, 256 threads / 8 warps, warp tile 64x64, 3-stage cp.async.
// TWO_PASS=1: A has hi/lo (2 MMA passes).  TWO_PASS=0: A hi only (1 pass).
#define TILE_B   16384               // 128 rows x 128 bytes
#define GTILE_BB 32768               // 256 rows x 128 bytes (B tile)
#define GSTAGE_B (2*TILE_B + GTILE_BB)
#define NSTG     3
#define GEMM_SMEM (NSTG*GSTAGE_B + 1024)

template<int OUT_HL, int TWO_PASS>
__global__ __launch_bounds__(256, 1) void gemm_hmma(
    const __half* __restrict__ Ahg, const __half* __restrict__ Alg,
    const __half* __restrict__ Bhg,
    float* __restrict__ C, __half* __restrict__ Ch, __half* __restrict__ Cl,
    int M, int N, int K, int scale_cols, float scale)
{
    extern __shared__ char smem[];
    const uint32_t tiles = (smem_u32(smem) + 1023) & ~1023u;
    const int tid = threadIdx.x, wid = tid >> 5, lane = tid & 31;
    const int m0 = blockIdx.y << 7, n0 = blockIdx.x << 8;
    const int wm = (wid & 1) << 6, wn = (wid >> 1) << 6;

    const __half* Ah = Ahg + (size_t)m0 * K;
    const __half* Al = Alg + (size_t)m0 * K;
    const __half* Bh = Bhg + (size_t)n0 * K;

    float acc[4][8][4];
    #pragma unroll
    for (int a = 0; a < 4; a++)
        #pragma unroll
        for (int b = 0; b < 8; b++)
            #pragma unroll
            for (int c = 0; c < 4; c++) acc[a][b][c] = 0.f;

    const int mat = lane >> 3, lr = lane & 7;
    const int rA = ((mat & 1) << 3) + lr, cA = (mat >> 1) << 4;
    const int rB = ((mat >> 1) << 3) + lr, cB = (mat & 1) << 4;

    auto load_stage = [&](int st, int k0) {
        const uint32_t base = tiles + st * GSTAGE_B;
        #pragma unroll
        for (int i = 0; i < 4; i++) {
            int idx = tid + (i << 8);
            int row = idx >> 3, c = idx & 7;
            uint32_t d = SWZ128(row * 128 + c * 16);
            CPA(base + d, Ah + (size_t)row * K + k0 + c * 8);
            if (TWO_PASS)
                CPA(base + TILE_B + d, Al + (size_t)row * K + k0 + c * 8);
        }
        #pragma unroll
        for (int i = 0; i < 8; i++) {
            int idx = tid + (i << 8);
            int row = idx >> 3, c = idx & 7;
            CPA(base + 2 * TILE_B + SWZ128(row * 128 + c * 16),
                Bh + (size_t)row * K + k0 + c * 8);
        }
    };

    const int NS = K >> 6;
    load_stage(0, 0);
    CP_COMMIT();
    load_stage(1, 64);
    CP_COMMIT();

    int sidx = 0;
    for (int s = 0; s < NS; s++) {
        CP_WAIT(1);
        __syncthreads();
        if (s + 2 < NS) {
            int nst = sidx + 2; if (nst >= NSTG) nst -= NSTG;
            load_stage(nst, (s + 2) * 64);
            CP_COMMIT();
        }
        const uint32_t sAh = tiles + sidx * GSTAGE_B;
        const uint32_t sAl = sAh + TILE_B;
        const uint32_t sBh = sAh + 2 * TILE_B;

        #pragma unroll
        for (int k16 = 0; k16 < 4; k16++) {
            uint32_t ah[4][4], al[4][4], bh[8][2];
            #pragma unroll
            for (int tm = 0; tm < 4; tm++) {
                uint32_t off = SWZ128((uint32_t)((wm + tm * 16 + rA) * 128 + cA + k16 * 32));
                LDSM_X4(ah[tm], sAh + off);
                if (TWO_PASS) LDSM_X4(al[tm], sAl + off);
            }
            #pragma unroll
            for (int p = 0; p < 4; p++) {
                uint32_t off = SWZ128((uint32_t)((wn + p * 16 + rB) * 128 + cB + k16 * 32));
                uint32_t t[4];
                LDSM_X4(t, sBh + off);
                bh[2*p][0] = t[0]; bh[2*p][1] = t[1];
                bh[2*p+1][0] = t[2]; bh[2*p+1][1] = t[3];
            }
            #pragma unroll
            for (int tm = 0; tm < 4; tm++)
                #pragma unroll
                for (int tn = 0; tn < 8; tn++) {
                    mma16816(acc[tm][tn], ah[tm], bh[tn]);
                    if (TWO_PASS) mma16816(acc[tm][tn], al[tm], bh[tn]);
                }
        }
        if (++sidx == NSTG) sidx = 0;
        __syncthreads();
    }

    const int lr4 = lane >> 2, lc2 = (lane & 3) << 1;
    #pragma unroll
    for (int tm = 0; tm < 4; tm++)
        #pragma unroll
        for (int tn = 0; tn < 8; tn++) {
            int gr = m0 + wm + tm * 16 + lr4;
            int gc = n0 + wn + tn * 8 + lc2;
            float sc = (gc < scale_cols) ? scale : 1.0f;
            float v0 = acc[tm][tn][0] * sc, v1 = acc[tm][tn][1] * sc;
            float v2 = acc[tm][tn][2] * sc, v3 = acc[tm][tn][3] * sc;
            if (OUT_HL) {
                write_hl2(Ch, Cl, (size_t)gr * N + gc, v0, v1);
                write_hl2(Ch, Cl, (size_t)(gr + 8) * N + gc, v2, v3);
            } else {
                float* c0 = C + (size_t)gr * N + gc;
                c0[0] = v0; c0[1] = v1;
                float* c1 = c0 + 8 * (size_t)N;
                c1[0] = v2; c1[1] = v3;
            }
        }
}

// ---------------- attn_sim (HMMA): sim = q @ k2^T, mask, relu^2, hi-only out ----------------
#define ASTAGE_B (4*TILE_B)
#define ASIM_SMEM (NSTG*ASTAGE_B + 1024)

__global__ __launch_bounds__(256, 1) void attn_sim_hmma(
    const __half* __restrict__ qkvh, const __half* __restrict__ qkvl,
    __half* __restrict__ awh)
{
    extern __shared__ char smem[];
    const uint32_t tiles = (smem_u32(smem) + 1023) & ~1023u;
    const int tid = threadIdx.x, wid = tid >> 5, lane = tid & 31;
    const int jhalf = blockIdx.x;
    const int blk = blockIdx.y;
    const int b = blk >> 6, wblk = blk & 63;
    const int qbase = b * TT + wblk * WSZ;
    const int krow0 = qbase - WSZ + jhalf * WSZ;
    const int bstart = b * TT;
    const int wm = (wid & 1) << 6, wn = (wid >> 1) << 5;

    float acc[4][4][4];
    #pragma unroll
    for (int a = 0; a < 4; a++)
        #pragma unroll
        for (int b2 = 0; b2 < 4; b2++)
            #pragma unroll
            for (int c = 0; c < 4; c++) acc[a][b2][c] = 0.f;

    const int mat = lane >> 3, lr = lane & 7;
    const int rA = ((mat & 1) << 3) + lr, cA = (mat >> 1) << 4;
    const int rB = ((mat >> 1) << 3) + lr, cB = (mat & 1) << 4;

    auto load_stage = [&](int st, int k0) {
        const uint32_t base = tiles + st * ASTAGE_B;
        #pragma unroll
        for (int i = 0; i < 4; i++) {
            int idx = tid + (i << 8);
            int row = idx >> 3, c = idx & 7;
            size_t qoff = (size_t)(qbase + row) * TDIM + k0 + c * 8;
            uint32_t d = SWZ128(row * 128 + c * 16);
            CPA(base + d, qkvh + qoff);
            CPA(base + TILE_B + d, qkvl + qoff);
            int grow = krow0 + row;
            bool ok = grow >= bstart;
            size_t koff = (size_t)grow * TDIM + DIM + k0 + c * 8;
            CPA_Z(base + 2 * TILE_B + d, qkvh + koff, ok);
            CPA_Z(base + 3 * TILE_B + d, qkvl + koff, ok);
        }
    };

    const int NS = DIM >> 6;
    load_stage(0, 0);
    CP_COMMIT();
    load_stage(1, 64);
    CP_COMMIT();

    int sidx = 0;
    for (int s = 0; s < NS; s++) {
        CP_WAIT(1);
        __syncthreads();
        if (s + 2 < NS) {
            int nst = sidx + 2; if (nst >= NSTG) nst -= NSTG;
            load_stage(nst, (s + 2) * 64);
            CP_COMMIT();
        }
        const uint32_t sQh = tiles + sidx * ASTAGE_B;
        const uint32_t sQl = sQh + TILE_B;
        const uint32_t sKh = sQh + 2 * TILE_B;
        const uint32_t sKl = sQh + 3 * TILE_B;

        #pragma unroll
        for (int k16 = 0; k16 < 4; k16++) {
            uint32_t ah[4][4], al[4][4], bh[4][2], bl[4][2];
            #pragma unroll
            for (int tm = 0; tm < 4; tm++) {
                uint32_t off = SWZ128((uint32_t)((wm + tm * 16 + rA) * 128 + cA + k16 * 32));
                LDSM_X4(ah[tm], sQh + off);
                LDSM_X4(al[tm], sQl + off);
            }
            #pragma unroll
            for (int p = 0; p < 2; p++) {
                uint32_t off = SWZ128((uint32_t)((wn + p * 16 + rB) * 128 + cB + k16 * 32));
                uint32_t t[4];
                LDSM_X4(t, sKh + off);
                bh[2*p][0] = t[0]; bh[2*p][1] = t[1];
                bh[2*p+1][0] = t[2]; bh[2*p+1][1] = t[3];
                LDSM_X4(t, sKl + off);
                bl[2*p][0] = t[0]; bl[2*p][1] = t[1];
                bl[2*p+1][0] = t[2]; bl[2*p+1][1] = t[3];
            }
            #pragma unroll
            for (int tm = 0; tm < 4; tm++)
                #pragma unroll
                for (int tn = 0; tn < 4; tn++) {
                    mma16816(acc[tm][tn], ah[tm], bh[tn]);
                    mma16816(acc[tm][tn], ah[tm], bl[tn]);
                    mma16816(acc[tm][tn], al[tm], bh[tn]);
                }
        }
        if (++sidx == NSTG) sidx = 0;
        __syncthreads();
    }

    const bool prevok = (wblk > 0);
    const int lr4 = lane >> 2, lc2 = (lane & 3) << 1;
    __half* oh = awh + (size_t)blk * WSZ * 256;
    #pragma unroll
    for (int tm = 0; tm < 4; tm++)
        #pragma unroll
        for (int tn = 0; tn < 4; tn++) {
            #pragma unroll
            for (int half8 = 0; half8 < 2; half8++) {
                int i = wm + tm * 16 + lr4 + half8 * 8;
                int jl = wn + tn * 8 + lc2;
                int j = (jhalf << 7) + jl;
                float r[2];
                #pragma unroll
                for (int u = 0; u < 2; u++) {
                    int jj = j + u;
                    bool keep = (jj >= i) && (jj <= i + WSZ) && (prevok || jj >= WSZ);
                    float sv = acc[tm][tn][half8 * 2 + u];
                    r[u] = (keep && sv > 0.f) ? sv * sv : 0.f;
                }
                write_h2(oh, (size_t)i * 256 + j, r[0], r[1]);
            }
        }
}

// ---------------- attn_out (HMMA): out = attn @ v2, single-pass, hi-only ----------------
#define VTILE_B  16384
#define OSTAGE_B (TILE_B + VTILE_B)
#define AOUT_SMEM (NSTG*OSTAGE_B + 1024)
#define SWZV(off) ((off) ^ ((((off) >> 8) & 7) << 4))

__global__ __launch_bounds__(256, 1) void attn_out_hmma(
    const __half* __restrict__ qkvh, const __half* __restrict__ awh,
    __half* __restrict__ ath)
{
    extern __shared__ char smem[];
    const uint32_t tiles = (smem_u32(smem) + 1023) & ~1023u;
    const int tid = threadIdx.x, wid = tid >> 5, lane = tid & 31;
    const int n0 = blockIdx.x << 7;
    const int blk = blockIdx.y;
    const int b = blk >> 6, wblk = blk & 63;
    const int qbase = b * TT + wblk * WSZ;
    const int krow0 = qbase - WSZ;
    const int bstart = b * TT;
    const int wm = (wid & 1) << 6, wn = (wid >> 1) << 5;

    const __half* Ah = awh + (size_t)blk * WSZ * 256;

    float acc[4][4][4];
    #pragma unroll
    for (int a = 0; a < 4; a++)
        #pragma unroll
        for (int b2 = 0; b2 < 4; b2++)
            #pragma unroll
            for (int c = 0; c < 4; c++) acc[a][b2][c] = 0.f;

    const int mat = lane >> 3, lr = lane & 7;
    const int rA = ((mat & 1) << 3) + lr, cA = (mat >> 1) << 4;

    auto load_stage = [&](int st, int k0) {
        const uint32_t base = tiles + st * OSTAGE_B;
        #pragma unroll
        for (int i = 0; i < 4; i++) {
            int idx = tid + (i << 8);
            int row = idx >> 3, c = idx & 7;
            size_t off = (size_t)row * 256 + k0 + c * 8;
            CPA(base + SWZ128(row * 128 + c * 16), Ah + off);
        }
        #pragma unroll
        for (int i = 0; i < 4; i++) {
            int idx = tid + (i << 8);
            int j = idx >> 4, c = idx & 15;
            int grow = krow0 + k0 + j;
            bool ok = grow >= bstart;
            size_t off = (size_t)grow * TDIM + 2 * DIM + n0 + c * 8;
            CPA_Z(base + TILE_B + SWZV((uint32_t)(j * 256 + c * 16)), qkvh + off, ok);
        }
    };

    const int NS = 4;
    load_stage(0, 0);
    CP_COMMIT();
    load_stage(1, 64);
    CP_COMMIT();

    int sidx = 0;
    for (int s = 0; s < NS; s++) {
        CP_WAIT(1);
        __syncthreads();
        if (s + 2 < NS) {
            int nst = sidx + 2; if (nst >= NSTG) nst -= NSTG;
            load_stage(nst, (s + 2) * 64);
            CP_COMMIT();
        }
        const uint32_t sAh = tiles + sidx * OSTAGE_B;
        const uint32_t sVh = sAh + TILE_B;

        #pragma unroll
        for (int k16 = 0; k16 < 4; k16++) {
            uint32_t ah[4][4], bh[4][2];
            #pragma unroll
            for (int tm = 0; tm < 4; tm++) {
                uint32_t off = SWZ128((uint32_t)((wm + tm * 16 + rA) * 128 + cA + k16 * 32));
                LDSM_X4(ah[tm], sAh + off);
            }
            #pragma unroll
            for (int p = 0; p < 2; p++) {
                int nn = wn + p * 16;
                uint32_t off = SWZV((uint32_t)((k16 * 16 + (lane & 15)) * 256 + (nn + ((lane >> 4) << 3)) * 2));
                uint32_t t[4];
                LDSM_X4_T(t, sVh + off);
                bh[2*p][0] = t[0]; bh[2*p][1] = t[1];
                bh[2*p+1][0] = t[2]; bh[2*p+1][1] = t[3];
            }
            #pragma unroll
            for (int tm = 0; tm < 4; tm++)
                #pragma unroll
                for (int tn = 0; tn < 4; tn++)
                    mma16816(acc[tm][tn], ah[tm], bh[tn]);
        }
        if (++sidx == NSTG) sidx = 0;
        __syncthreads();
    }

    const int lr4 = lane >> 2, lc2 = (lane & 3) << 1;
    #pragma unroll
    for (int tm = 0; tm < 4; tm++)
        #pragma unroll
        for (int tn = 0; tn < 4; tn++) {
            int gr = qbase + wm + tm * 16 + lr4;
            int gc = n0 + wn + tn * 8 + lc2;
            write_h2(ath, (size_t)gr * DIM + gc, acc[tm][tn][0], acc[tm][tn][1]);
            write_h2(ath, (size_t)(gr + 8) * DIM + gc, acc[tm][tn][2], acc[tm][tn][3]);
        }
}

// ---------------------------------------------------------------------------
extern "C" void kernel_launch(void* const* d_in, const int* in_sizes, int n_in,
                              void* d_out, int out_size)
{
    (void)in_sizes; (void)n_in; (void)out_size;
    const float* x      = (const float*)d_in[0];
    const float* w_attn = (const float*)d_in[1];
    const float* w_o    = (const float*)d_in[2];
    float* out = (float*)d_out;

    __half *xh, *xl, *wah, *woh, *qkvh, *qkvl, *awh, *ath;
    cudaGetSymbolAddress((void**)&xh,   g_xh);   cudaGetSymbolAddress((void**)&xl,   g_xl);
    cudaGetSymbolAddress((void**)&wah,  g_wah);  cudaGetSymbolAddress((void**)&woh,  g_woh);
    cudaGetSymbolAddress((void**)&qkvh, g_qkvh); cudaGetSymbolAddress((void**)&qkvl, g_qkvl);
    cudaGetSymbolAddress((void**)&awh,  g_awh);
    cudaGetSymbolAddress((void**)&ath,  g_ath);

    cudaFuncSetAttribute((const void*)gemm_hmma<1,1>, cudaFuncAttributeMaxDynamicSharedMemorySize, GEMM_SMEM);
    cudaFuncSetAttribute((const void*)gemm_hmma<0,0>, cudaFuncAttributeMaxDynamicSharedMemorySize, GEMM_SMEM);
    cudaFuncSetAttribute((const void*)attn_sim_hmma, cudaFuncAttributeMaxDynamicSharedMemorySize, ASIM_SMEM);
    cudaFuncSetAttribute((const void*)attn_out_hmma, cudaFuncAttributeMaxDynamicSharedMemorySize, AOUT_SMEM);

    // 0) fp16 splits
    {
        int n4 = MROWS * DIM / 4;
        split_hl_kernel<<<(n4 + 255) / 256, 256>>>(x, xh, xl, n4);
        n4 = TDIM * DIM / 4;
        split_h_kernel<<<(n4 + 255) / 256, 256>>>(w_attn, wah, n4);
        n4 = DIM * DIM / 4;
        split_h_kernel<<<(n4 + 255) / 256, 256>>>(w_o, woh, n4);
    }

    // 1) qkv = x @ w_attn^T -> hi/lo fp16  (q cols scaled by 1/W)  [2-pass]
    gemm_hmma<1,1><<<dim3(TDIM / 256, MROWS / 128), 256, GEMM_SMEM>>>(
        xh, xl, wah, nullptr, qkvh, qkvl, MROWS, TDIM, DIM, DIM, 1.0f / (float)WSZ);

    // 2) attention weights (3-pass HMMA) -> hi-only fp16
    attn_sim_hmma<<<dim3(2, NBLK), 256, ASIM_SMEM>>>(qkvh, qkvl, awh);

    // 3) attn @ v (single-pass HMMA) -> hi-only fp16
    attn_out_hmma<<<dim3(DIM / 128, NBLK), 256, AOUT_SMEM>>>(qkvh, awh, ath);

    // 4) out = att @ w_o^T -> fp32  [single-pass]
    gemm_hmma<0,0><<<dim3(DIM / 256, MROWS / 128), 256, GEMM_SMEM>>>(
        ath, ath, woh, out, nullptr, nullptr, MROWS, DIM, DIM, 0, 1.0f);
}

// round 11
// speedup vs baseline: 1.7885x; 1.4469x over previous
#include <cuda_runtime.h>
#include <cuda_fp16.h>
#include <cstdint>
#include <cstddef>

#define DIM   2048
#define TDIM  6144
#define BB    2
#define TT    8192
#define MROWS (BB*TT)
#define WSZ   128
#define NBLK  (MROWS/WSZ)

// ---------------- scratch (static device globals) ----------------
__device__ __half g_xh[(size_t)MROWS * DIM];
__device__ __half g_wah[(size_t)TDIM * DIM];
__device__ __half g_woh[(size_t)DIM * DIM];
__device__ __half g_qkvh[(size_t)MROWS * TDIM];
__device__ __half g_qkvl[(size_t)MROWS * TDIM];
__device__ __half g_awh[(size_t)NBLK * WSZ * 256];
__device__ __half g_ath[(size_t)MROWS * DIM];

// ---------------- helpers ----------------
__device__ __forceinline__ uint32_t smem_u32(const void* p) {
    uint32_t a;
    asm("{ .reg .u64 t; cvta.to.shared.u64 t, %1; cvt.u32.u64 %0, t; }" : "=r"(a) : "l"(p));
    return a;
}
#define SWZ128(o) ((o) ^ (((o) >> 3) & 0x70))

#define LDSM_X4(r, a) \
    asm volatile("ldmatrix.sync.aligned.m8n8.x4.shared.b16 {%0,%1,%2,%3}, [%4];" \
        : "=r"((r)[0]), "=r"((r)[1]), "=r"((r)[2]), "=r"((r)[3]) : "r"(a))
#define LDSM_X4_T(r, a) \
    asm volatile("ldmatrix.sync.aligned.m8n8.x4.trans.shared.b16 {%0,%1,%2,%3}, [%4];" \
        : "=r"((r)[0]), "=r"((r)[1]), "=r"((r)[2]), "=r"((r)[3]) : "r"(a))

__device__ __forceinline__ void mma16816(float* d, const uint32_t* a, const uint32_t* b) {
    asm volatile("mma.sync.aligned.m16n8k16.row.col.f32.f16.f16.f32 "
        "{%0,%1,%2,%3}, {%4,%5,%6,%7}, {%8,%9}, {%0,%1,%2,%3};"
        : "+f"(d[0]), "+f"(d[1]), "+f"(d[2]), "+f"(d[3])
        : "r"(a[0]), "r"(a[1]), "r"(a[2]), "r"(a[3]), "r"(b[0]), "r"(b[1]));
}

#define CPA(dst, src) \
    asm volatile("cp.async.cg.shared.global [%0], [%1], 16;" :: "r"(dst), "l"(src))
#define CPA_Z(dst, src, pred) \
    asm volatile("cp.async.cg.shared.global [%0], [%1], 16, %2;" :: "r"(dst), "l"(src), "r"((pred) ? 16 : 0))
#define CP_COMMIT() asm volatile("cp.async.commit_group;" ::: "memory")
#define CP_WAIT(n)  asm volatile("cp.async.wait_group %0;" :: "n"(n) : "memory")

__device__ __forceinline__ void write_hl2(__half* H, __half* L, size_t idx, float v0, float v1) {
    __half h0 = __float2half_rn(v0), h1 = __float2half_rn(v1);
    __half l0 = __float2half_rn(v0 - __half2float(h0));
    __half l1 = __float2half_rn(v1 - __half2float(h1));
    *(__half2*)(H + idx) = __halves2half2(h0, h1);
    *(__half2*)(L + idx) = __halves2half2(l0, l1);
}
__device__ __forceinline__ void write_h2(__half* H, size_t idx, float v0, float v1) {
    *(__half2*)(H + idx) = __halves2half2(__float2half_rn(v0), __float2half_rn(v1));
}

// ---------------- fp32 -> fp16 split (hi only) ----------------
__global__ __launch_bounds__(256) void split_h_kernel(
    const float* __restrict__ src, __half* __restrict__ hi, int n4)
{
    int i = blockIdx.x * blockDim.x + threadIdx.x;
    if (i >= n4) return;
    float4 v = ((const float4*)src)[i];
    float vv[4] = {v.x, v.y, v.z, v.w};
    __half h4[4];
    #pragma unroll
    for (int j = 0; j < 4; j++) h4[j] = __float2half_rn(vv[j]);
    ((uint2*)hi)[i] = *(uint2*)h4;
}

// ---------------- split-fp16 HMMA GEMM: C = A @ B^T ----------------
// 128x256 CTA tile, 256 threads / 8 warps, warp tile 64x64, 3-stage cp.async.
// TWO_PASS=1: A has hi/lo (2 MMA passes).  TWO_PASS=0: A hi only (1 pass).
#define TILE_B   16384               // 128 rows x 128 bytes
#define GTILE_BB 32768               // 256 rows x 128 bytes (B tile)
#define GSTAGE_B (2*TILE_B + GTILE_BB)
#define NSTG     3
#define GEMM_SMEM (NSTG*GSTAGE_B + 1024)

template<int OUT_HL, int TWO_PASS>
__global__ __launch_bounds__(256, 1) void gemm_hmma(
    const __half* __restrict__ Ahg, const __half* __restrict__ Alg,
    const __half* __restrict__ Bhg,
    float* __restrict__ C, __half* __restrict__ Ch, __half* __restrict__ Cl,
    int M, int N, int K, int scale_cols, float scale)
{
    extern __shared__ char smem[];
    const uint32_t tiles = (smem_u32(smem) + 1023) & ~1023u;
    const int tid = threadIdx.x, wid = tid >> 5, lane = tid & 31;
    const int m0 = blockIdx.y << 7, n0 = blockIdx.x << 8;
    const int wm = (wid & 1) << 6, wn = (wid >> 1) << 6;

    const __half* Ah = Ahg + (size_t)m0 * K;
    const __half* Al = Alg + (size_t)m0 * K;
    const __half* Bh = Bhg + (size_t)n0 * K;

    float acc[4][8][4];
    #pragma unroll
    for (int a = 0; a < 4; a++)
        #pragma unroll
        for (int b = 0; b < 8; b++)
            #pragma unroll
            for (int c = 0; c < 4; c++) acc[a][b][c] = 0.f;

    const int mat = lane >> 3, lr = lane & 7;
    const int rA = ((mat & 1) << 3) + lr, cA = (mat >> 1) << 4;
    const int rB = ((mat >> 1) << 3) + lr, cB = (mat & 1) << 4;

    auto load_stage = [&](int st, int k0) {
        const uint32_t base = tiles + st * GSTAGE_B;
        #pragma unroll
        for (int i = 0; i < 4; i++) {
            int idx = tid + (i << 8);
            int row = idx >> 3, c = idx & 7;
            uint32_t d = SWZ128(row * 128 + c * 16);
            CPA(base + d, Ah + (size_t)row * K + k0 + c * 8);
            if (TWO_PASS)
                CPA(base + TILE_B + d, Al + (size_t)row * K + k0 + c * 8);
        }
        #pragma unroll
        for (int i = 0; i < 8; i++) {
            int idx = tid + (i << 8);
            int row = idx >> 3, c = idx & 7;
            CPA(base + 2 * TILE_B + SWZ128(row * 128 + c * 16),
                Bh + (size_t)row * K + k0 + c * 8);
        }
    };

    const int NS = K >> 6;
    load_stage(0, 0);
    CP_COMMIT();
    load_stage(1, 64);
    CP_COMMIT();

    int sidx = 0;
    for (int s = 0; s < NS; s++) {
        CP_WAIT(1);
        __syncthreads();
        if (s + 2 < NS) {
            int nst = sidx + 2; if (nst >= NSTG) nst -= NSTG;
            load_stage(nst, (s + 2) * 64);
            CP_COMMIT();
        }
        const uint32_t sAh = tiles + sidx * GSTAGE_B;
        const uint32_t sAl = sAh + TILE_B;
        const uint32_t sBh = sAh + 2 * TILE_B;

        #pragma unroll
        for (int k16 = 0; k16 < 4; k16++) {
            uint32_t ah[4][4], al[4][4], bh[8][2];
            #pragma unroll
            for (int tm = 0; tm < 4; tm++) {
                uint32_t off = SWZ128((uint32_t)((wm + tm * 16 + rA) * 128 + cA + k16 * 32));
                LDSM_X4(ah[tm], sAh + off);
                if (TWO_PASS) LDSM_X4(al[tm], sAl + off);
            }
            #pragma unroll
            for (int p = 0; p < 4; p++) {
                uint32_t off = SWZ128((uint32_t)((wn + p * 16 + rB) * 128 + cB + k16 * 32));
                uint32_t t[4];
                LDSM_X4(t, sBh + off);
                bh[2*p][0] = t[0]; bh[2*p][1] = t[1];
                bh[2*p+1][0] = t[2]; bh[2*p+1][1] = t[3];
            }
            #pragma unroll
            for (int tm = 0; tm < 4; tm++)
                #pragma unroll
                for (int tn = 0; tn < 8; tn++) {
                    mma16816(acc[tm][tn], ah[tm], bh[tn]);
                    if (TWO_PASS) mma16816(acc[tm][tn], al[tm], bh[tn]);
                }
        }
        if (++sidx == NSTG) sidx = 0;
        __syncthreads();
    }

    const int lr4 = lane >> 2, lc2 = (lane & 3) << 1;
    #pragma unroll
    for (int tm = 0; tm < 4; tm++)
        #pragma unroll
        for (int tn = 0; tn < 8; tn++) {
            int gr = m0 + wm + tm * 16 + lr4;
            int gc = n0 + wn + tn * 8 + lc2;
            float sc = (gc < scale_cols) ? scale : 1.0f;
            float v0 = acc[tm][tn][0] * sc, v1 = acc[tm][tn][1] * sc;
            float v2 = acc[tm][tn][2] * sc, v3 = acc[tm][tn][3] * sc;
            if (OUT_HL) {
                write_hl2(Ch, Cl, (size_t)gr * N + gc, v0, v1);
                write_hl2(Ch, Cl, (size_t)(gr + 8) * N + gc, v2, v3);
            } else {
                float* c0 = C + (size_t)gr * N + gc;
                c0[0] = v0; c0[1] = v1;
                float* c1 = c0 + 8 * (size_t)N;
                c1[0] = v2; c1[1] = v3;
            }
        }
}

// ---------------- attn_sim (HMMA): sim = q @ k2^T, mask, relu^2, hi-only out ----------------
#define ASTAGE_B (4*TILE_B)
#define ASIM_SMEM (NSTG*ASTAGE_B + 1024)

__global__ __launch_bounds__(256, 1) void attn_sim_hmma(
    const __half* __restrict__ qkvh, const __half* __restrict__ qkvl,
    __half* __restrict__ awh)
{
    extern __shared__ char smem[];
    const uint32_t tiles = (smem_u32(smem) + 1023) & ~1023u;
    const int tid = threadIdx.x, wid = tid >> 5, lane = tid & 31;
    const int jhalf = blockIdx.x;
    const int blk = blockIdx.y;
    const int b = blk >> 6, wblk = blk & 63;
    const int qbase = b * TT + wblk * WSZ;
    const int krow0 = qbase - WSZ + jhalf * WSZ;
    const int bstart = b * TT;
    const int wm = (wid & 1) << 6, wn = (wid >> 1) << 5;

    float acc[4][4][4];
    #pragma unroll
    for (int a = 0; a < 4; a++)
        #pragma unroll
        for (int b2 = 0; b2 < 4; b2++)
            #pragma unroll
            for (int c = 0; c < 4; c++) acc[a][b2][c] = 0.f;

    const int mat = lane >> 3, lr = lane & 7;
    const int rA = ((mat & 1) << 3) + lr, cA = (mat >> 1) << 4;
    const int rB = ((mat >> 1) << 3) + lr, cB = (mat & 1) << 4;

    auto load_stage = [&](int st, int k0) {
        const uint32_t base = tiles + st * ASTAGE_B;
        #pragma unroll
        for (int i = 0; i < 4; i++) {
            int idx = tid + (i << 8);
            int row = idx >> 3, c = idx & 7;
            size_t qoff = (size_t)(qbase + row) * TDIM + k0 + c * 8;
            uint32_t d = SWZ128(row * 128 + c * 16);
            CPA(base + d, qkvh + qoff);
            CPA(base + TILE_B + d, qkvl + qoff);
            int grow = krow0 + row;
            bool ok = grow >= bstart;
            size_t koff = (size_t)grow * TDIM + DIM + k0 + c * 8;
            CPA_Z(base + 2 * TILE_B + d, qkvh + koff, ok);
            CPA_Z(base + 3 * TILE_B + d, qkvl + koff, ok);
        }
    };

    const int NS = DIM >> 6;
    load_stage(0, 0);
    CP_COMMIT();
    load_stage(1, 64);
    CP_COMMIT();

    int sidx = 0;
    for (int s = 0; s < NS; s++) {
        CP_WAIT(1);
        __syncthreads();
        if (s + 2 < NS) {
            int nst = sidx + 2; if (nst >= NSTG) nst -= NSTG;
            load_stage(nst, (s + 2) * 64);
            CP_COMMIT();
        }
        const uint32_t sQh = tiles + sidx * ASTAGE_B;
        const uint32_t sQl = sQh + TILE_B;
        const uint32_t sKh = sQh + 2 * TILE_B;
        const uint32_t sKl = sQh + 3 * TILE_B;

        #pragma unroll
        for (int k16 = 0; k16 < 4; k16++) {
            uint32_t ah[4][4], al[4][4], bh[4][2], bl[4][2];
            #pragma unroll
            for (int tm = 0; tm < 4; tm++) {
                uint32_t off = SWZ128((uint32_t)((wm + tm * 16 + rA) * 128 + cA + k16 * 32));
                LDSM_X4(ah[tm], sQh + off);
                LDSM_X4(al[tm], sQl + off);
            }
            #pragma unroll
            for (int p = 0; p < 2; p++) {
                uint32_t off = SWZ128((uint32_t)((wn + p * 16 + rB) * 128 + cB + k16 * 32));
                uint32_t t[4];
                LDSM_X4(t, sKh + off);
                bh[2*p][0] = t[0]; bh[2*p][1] = t[1];
                bh[2*p+1][0] = t[2]; bh[2*p+1][1] = t[3];
                LDSM_X4(t, sKl + off);
                bl[2*p][0] = t[0]; bl[2*p][1] = t[1];
                bl[2*p+1][0] = t[2]; bl[2*p+1][1] = t[3];
            }
            #pragma unroll
            for (int tm = 0; tm < 4; tm++)
                #pragma unroll
                for (int tn = 0; tn < 4; tn++) {
                    mma16816(acc[tm][tn], ah[tm], bh[tn]);
                    mma16816(acc[tm][tn], ah[tm], bl[tn]);
                    mma16816(acc[tm][tn], al[tm], bh[tn]);
                }
        }
        if (++sidx == NSTG) sidx = 0;
        __syncthreads();
    }

    const bool prevok = (wblk > 0);
    const int lr4 = lane >> 2, lc2 = (lane & 3) << 1;
    __half* oh = awh + (size_t)blk * WSZ * 256;
    #pragma unroll
    for (int tm = 0; tm < 4; tm++)
        #pragma unroll
        for (int tn = 0; tn < 4; tn++) {
            #pragma unroll
            for (int half8 = 0; half8 < 2; half8++) {
                int i = wm + tm * 16 + lr4 + half8 * 8;
                int jl = wn + tn * 8 + lc2;
                int j = (jhalf << 7) + jl;
                float r[2];
                #pragma unroll
                for (int u = 0; u < 2; u++) {
                    int jj = j + u;
                    bool keep = (jj >= i) && (jj <= i + WSZ) && (prevok || jj >= WSZ);
                    float sv = acc[tm][tn][half8 * 2 + u];
                    r[u] = (keep && sv > 0.f) ? sv * sv : 0.f;
                }
                write_h2(oh, (size_t)i * 256 + j, r[0], r[1]);
            }
        }
}

// ---------------- attn_out (HMMA): out = attn @ v2, single-pass, hi-only ----------------
#define VTILE_B  16384
#define OSTAGE_B (TILE_B + VTILE_B)
#define AOUT_SMEM (NSTG*OSTAGE_B + 1024)
#define SWZV(off) ((off) ^ ((((off) >> 8) & 7) << 4))

__global__ __launch_bounds__(256, 1) void attn_out_hmma(
    const __half* __restrict__ qkvh, const __half* __restrict__ awh,
    __half* __restrict__ ath)
{
    extern __shared__ char smem[];
    const uint32_t tiles = (smem_u32(smem) + 1023) & ~1023u;
    const int tid = threadIdx.x, wid = tid >> 5, lane = tid & 31;
    const int n0 = blockIdx.x << 7;
    const int blk = blockIdx.y;
    const int b = blk >> 6, wblk = blk & 63;
    const int qbase = b * TT + wblk * WSZ;
    const int krow0 = qbase - WSZ;
    const int bstart = b * TT;
    const int wm = (wid & 1) << 6, wn = (wid >> 1) << 5;

    const __half* Ah = awh + (size_t)blk * WSZ * 256;

    float acc[4][4][4];
    #pragma unroll
    for (int a = 0; a < 4; a++)
        #pragma unroll
        for (int b2 = 0; b2 < 4; b2++)
            #pragma unroll
            for (int c = 0; c < 4; c++) acc[a][b2][c] = 0.f;

    const int mat = lane >> 3, lr = lane & 7;
    const int rA = ((mat & 1) << 3) + lr, cA = (mat >> 1) << 4;

    auto load_stage = [&](int st, int k0) {
        const uint32_t base = tiles + st * OSTAGE_B;
        #pragma unroll
        for (int i = 0; i < 4; i++) {
            int idx = tid + (i << 8);
            int row = idx >> 3, c = idx & 7;
            size_t off = (size_t)row * 256 + k0 + c * 8;
            CPA(base + SWZ128(row * 128 + c * 16), Ah + off);
        }
        #pragma unroll
        for (int i = 0; i < 4; i++) {
            int idx = tid + (i << 8);
            int j = idx >> 4, c = idx & 15;
            int grow = krow0 + k0 + j;
            bool ok = grow >= bstart;
            size_t off = (size_t)grow * TDIM + 2 * DIM + n0 + c * 8;
            CPA_Z(base + TILE_B + SWZV((uint32_t)(j * 256 + c * 16)), qkvh + off, ok);
        }
    };

    const int NS = 4;
    load_stage(0, 0);
    CP_COMMIT();
    load_stage(1, 64);
    CP_COMMIT();

    int sidx = 0;
    for (int s = 0; s < NS; s++) {
        CP_WAIT(1);
        __syncthreads();
        if (s + 2 < NS) {
            int nst = sidx + 2; if (nst >= NSTG) nst -= NSTG;
            load_stage(nst, (s + 2) * 64);
            CP_COMMIT();
        }
        const uint32_t sAh = tiles + sidx * OSTAGE_B;
        const uint32_t sVh = sAh + TILE_B;

        #pragma unroll
        for (int k16 = 0; k16 < 4; k16++) {
            uint32_t ah[4][4], bh[4][2];
            #pragma unroll
            for (int tm = 0; tm < 4; tm++) {
                uint32_t off = SWZ128((uint32_t)((wm + tm * 16 + rA) * 128 + cA + k16 * 32));
                LDSM_X4(ah[tm], sAh + off);
            }
            #pragma unroll
            for (int p = 0; p < 2; p++) {
                int nn = wn + p * 16;
                uint32_t off = SWZV((uint32_t)((k16 * 16 + (lane & 15)) * 256 + (nn + ((lane >> 4) << 3)) * 2));
                uint32_t t[4];
                LDSM_X4_T(t, sVh + off);
                bh[2*p][0] = t[0]; bh[2*p][1] = t[1];
                bh[2*p+1][0] = t[2]; bh[2*p+1][1] = t[3];
            }
            #pragma unroll
            for (int tm = 0; tm < 4; tm++)
                #pragma unroll
                for (int tn = 0; tn < 4; tn++)
                    mma16816(acc[tm][tn], ah[tm], bh[tn]);
        }
        if (++sidx == NSTG) sidx = 0;
        __syncthreads();
    }

    const int lr4 = lane >> 2, lc2 = (lane & 3) << 1;
    #pragma unroll
    for (int tm = 0; tm < 4; tm++)
        #pragma unroll
        for (int tn = 0; tn < 4; tn++) {
            int gr = qbase + wm + tm * 16 + lr4;
            int gc = n0 + wn + tn * 8 + lc2;
            write_h2(ath, (size_t)gr * DIM + gc, acc[tm][tn][0], acc[tm][tn][1]);
            write_h2(ath, (size_t)(gr + 8) * DIM + gc, acc[tm][tn][2], acc[tm][tn][3]);
        }
}

// ---------------------------------------------------------------------------
extern "C" void kernel_launch(void* const* d_in, const int* in_sizes, int n_in,
                              void* d_out, int out_size)
{
    (void)in_sizes; (void)n_in; (void)out_size;
    const float* x      = (const float*)d_in[0];
    const float* w_attn = (const float*)d_in[1];
    const float* w_o    = (const float*)d_in[2];
    float* out = (float*)d_out;

    __half *xh, *wah, *woh, *qkvh, *qkvl, *awh, *ath;
    cudaGetSymbolAddress((void**)&xh,   g_xh);
    cudaGetSymbolAddress((void**)&wah,  g_wah);  cudaGetSymbolAddress((void**)&woh,  g_woh);
    cudaGetSymbolAddress((void**)&qkvh, g_qkvh); cudaGetSymbolAddress((void**)&qkvl, g_qkvl);
    cudaGetSymbolAddress((void**)&awh,  g_awh);
    cudaGetSymbolAddress((void**)&ath,  g_ath);

    cudaFuncSetAttribute((const void*)gemm_hmma<1,0>, cudaFuncAttributeMaxDynamicSharedMemorySize, GEMM_SMEM);
    cudaFuncSetAttribute((const void*)gemm_hmma<0,0>, cudaFuncAttributeMaxDynamicSharedMemorySize, GEMM_SMEM);
    cudaFuncSetAttribute((const void*)attn_sim_hmma, cudaFuncAttributeMaxDynamicSharedMemorySize, ASIM_SMEM);
    cudaFuncSetAttribute((const void*)attn_out_hmma, cudaFuncAttributeMaxDynamicSharedMemorySize, AOUT_SMEM);

    // 0) fp16 splits (hi only everywhere)
    {
        int n4 = MROWS * DIM / 4;
        split_h_kernel<<<(n4 + 255) / 256, 256>>>(x, xh, n4);
        n4 = TDIM * DIM / 4;
        split_h_kernel<<<(n4 + 255) / 256, 256>>>(w_attn, wah, n4);
        n4 = DIM * DIM / 4;
        split_h_kernel<<<(n4 + 255) / 256, 256>>>(w_o, woh, n4);
    }

    // 1) qkv = x @ w_attn^T -> hi/lo fp16  (q cols scaled by 1/W)  [single-pass]
    gemm_hmma<1,0><<<dim3(TDIM / 256, MROWS / 128), 256, GEMM_SMEM>>>(
        xh, xh, wah, nullptr, qkvh, qkvl, MROWS, TDIM, DIM, DIM, 1.0f / (float)WSZ);

    // 2) attention weights (3-pass HMMA on qkv hi/lo) -> hi-only fp16
    attn_sim_hmma<<<dim3(2, NBLK), 256, ASIM_SMEM>>>(qkvh, qkvl, awh);

    // 3) attn @ v (single-pass HMMA) -> hi-only fp16
    attn_out_hmma<<<dim3(DIM / 128, NBLK), 256, AOUT_SMEM>>>(qkvh, awh, ath);

    // 4) out = att @ w_o^T -> fp32  [single-pass]
    gemm_hmma<0,0><<<dim3(DIM / 256, MROWS / 128), 256, GEMM_SMEM>>>(
        ath, ath, woh, out, nullptr, nullptr, MROWS, DIM, DIM, 0, 1.0f);
}

// round 12
// speedup vs baseline: 1.8994x; 1.0620x over previous
#include <cuda_runtime.h>
#include <cuda_fp16.h>
#include <cstdint>
#include <cstddef>

#define DIM   2048
#define TDIM  6144
#define BB    2
#define TT    8192
#define MROWS (BB*TT)
#define WSZ   128
#define NBLK  (MROWS/WSZ)

// ---------------- scratch (static device globals) ----------------
__device__ __half g_xh[(size_t)MROWS * DIM];
__device__ __half g_wah[(size_t)TDIM * DIM];
__device__ __half g_woh[(size_t)DIM * DIM];
__device__ __half g_qkvh[(size_t)MROWS * TDIM];
__device__ __half g_qkvl[(size_t)MROWS * TDIM];   // only k-region cols [2048,4096) valid
__device__ __half g_awh[(size_t)NBLK * WSZ * 256];
__device__ __half g_ath[(size_t)MROWS * DIM];

// ---------------- helpers ----------------
__device__ __forceinline__ uint32_t smem_u32(const void* p) {
    uint32_t a;
    asm("{ .reg .u64 t; cvta.to.shared.u64 t, %1; cvt.u32.u64 %0, t; }" : "=r"(a) : "l"(p));
    return a;
}
#define SWZ128(o) ((o) ^ (((o) >> 3) & 0x70))

#define LDSM_X4(r, a) \
    asm volatile("ldmatrix.sync.aligned.m8n8.x4.shared.b16 {%0,%1,%2,%3}, [%4];" \
        : "=r"((r)[0]), "=r"((r)[1]), "=r"((r)[2]), "=r"((r)[3]) : "r"(a))
#define LDSM_X4_T(r, a) \
    asm volatile("ldmatrix.sync.aligned.m8n8.x4.trans.shared.b16 {%0,%1,%2,%3}, [%4];" \
        : "=r"((r)[0]), "=r"((r)[1]), "=r"((r)[2]), "=r"((r)[3]) : "r"(a))

__device__ __forceinline__ void mma16816(float* d, const uint32_t* a, const uint32_t* b) {
    asm volatile("mma.sync.aligned.m16n8k16.row.col.f32.f16.f16.f32 "
        "{%0,%1,%2,%3}, {%4,%5,%6,%7}, {%8,%9}, {%0,%1,%2,%3};"
        : "+f"(d[0]), "+f"(d[1]), "+f"(d[2]), "+f"(d[3])
        : "r"(a[0]), "r"(a[1]), "r"(a[2]), "r"(a[3]), "r"(b[0]), "r"(b[1]));
}

#define CPA(dst, src) \
    asm volatile("cp.async.cg.shared.global [%0], [%1], 16;" :: "r"(dst), "l"(src))
#define CPA_Z(dst, src, pred) \
    asm volatile("cp.async.cg.shared.global [%0], [%1], 16, %2;" :: "r"(dst), "l"(src), "r"((pred) ? 16 : 0))
#define CP_COMMIT() asm volatile("cp.async.commit_group;" ::: "memory")
#define CP_WAIT(n)  asm volatile("cp.async.wait_group %0;" :: "n"(n) : "memory")

__device__ __forceinline__ void write_hl2(__half* H, __half* L, size_t idx, float v0, float v1) {
    __half h0 = __float2half_rn(v0), h1 = __float2half_rn(v1);
    __half l0 = __float2half_rn(v0 - __half2float(h0));
    __half l1 = __float2half_rn(v1 - __half2float(h1));
    *(__half2*)(H + idx) = __halves2half2(h0, h1);
    *(__half2*)(L + idx) = __halves2half2(l0, l1);
}
__device__ __forceinline__ void write_h2(__half* H, size_t idx, float v0, float v1) {
    *(__half2*)(H + idx) = __halves2half2(__float2half_rn(v0), __float2half_rn(v1));
}

// ---------------- fp32 -> fp16 split (hi only) ----------------
__global__ __launch_bounds__(256) void split_h_kernel(
    const float* __restrict__ src, __half* __restrict__ hi, int n4)
{
    int i = blockIdx.x * blockDim.x + threadIdx.x;
    if (i >= n4) return;
    float4 v = ((const float4*)src)[i];
    float vv[4] = {v.x, v.y, v.z, v.w};
    __half h4[4];
    #pragma unroll
    for (int j = 0; j < 4; j++) h4[j] = __float2half_rn(vv[j]);
    ((uint2*)hi)[i] = *(uint2*)h4;
}

// ---------------- split-fp16 HMMA GEMM: C = A @ B^T ----------------
// 128x256 CTA tile, 256 threads / 8 warps, warp tile 64x64, 3-stage cp.async.
// OUT_HL=1: write hi everywhere, lo only for cols in [lo_c0, lo_c1).
#define TILE_B   16384               // 128 rows x 128 bytes
#define GTILE_BB 32768               // 256 rows x 128 bytes (B tile)
#define GSTAGE_B (2*TILE_B + GTILE_BB)
#define NSTG     3
#define GEMM_SMEM (NSTG*GSTAGE_B + 1024)

template<int OUT_HL, int TWO_PASS>
__global__ __launch_bounds__(256, 1) void gemm_hmma(
    const __half* __restrict__ Ahg, const __half* __restrict__ Alg,
    const __half* __restrict__ Bhg,
    float* __restrict__ C, __half* __restrict__ Ch, __half* __restrict__ Cl,
    int M, int N, int K, int scale_cols, float scale, int lo_c0, int lo_c1)
{
    extern __shared__ char smem[];
    const uint32_t tiles = (smem_u32(smem) + 1023) & ~1023u;
    const int tid = threadIdx.x, wid = tid >> 5, lane = tid & 31;
    const int m0 = blockIdx.y << 7, n0 = blockIdx.x << 8;
    const int wm = (wid & 1) << 6, wn = (wid >> 1) << 6;

    const __half* Ah = Ahg + (size_t)m0 * K;
    const __half* Al = Alg + (size_t)m0 * K;
    const __half* Bh = Bhg + (size_t)n0 * K;

    float acc[4][8][4];
    #pragma unroll
    for (int a = 0; a < 4; a++)
        #pragma unroll
        for (int b = 0; b < 8; b++)
            #pragma unroll
            for (int c = 0; c < 4; c++) acc[a][b][c] = 0.f;

    const int mat = lane >> 3, lr = lane & 7;
    const int rA = ((mat & 1) << 3) + lr, cA = (mat >> 1) << 4;
    const int rB = ((mat >> 1) << 3) + lr, cB = (mat & 1) << 4;

    auto load_stage = [&](int st, int k0) {
        const uint32_t base = tiles + st * GSTAGE_B;
        #pragma unroll
        for (int i = 0; i < 4; i++) {
            int idx = tid + (i << 8);
            int row = idx >> 3, c = idx & 7;
            uint32_t d = SWZ128(row * 128 + c * 16);
            CPA(base + d, Ah + (size_t)row * K + k0 + c * 8);
            if (TWO_PASS)
                CPA(base + TILE_B + d, Al + (size_t)row * K + k0 + c * 8);
        }
        #pragma unroll
        for (int i = 0; i < 8; i++) {
            int idx = tid + (i << 8);
            int row = idx >> 3, c = idx & 7;
            CPA(base + 2 * TILE_B + SWZ128(row * 128 + c * 16),
                Bh + (size_t)row * K + k0 + c * 8);
        }
    };

    const int NS = K >> 6;
    load_stage(0, 0);
    CP_COMMIT();
    load_stage(1, 64);
    CP_COMMIT();

    int sidx = 0;
    for (int s = 0; s < NS; s++) {
        CP_WAIT(1);
        __syncthreads();
        if (s + 2 < NS) {
            int nst = sidx + 2; if (nst >= NSTG) nst -= NSTG;
            load_stage(nst, (s + 2) * 64);
            CP_COMMIT();
        }
        const uint32_t sAh = tiles + sidx * GSTAGE_B;
        const uint32_t sAl = sAh + TILE_B;
        const uint32_t sBh = sAh + 2 * TILE_B;

        #pragma unroll
        for (int k16 = 0; k16 < 4; k16++) {
            uint32_t ah[4][4], al[4][4], bh[8][2];
            #pragma unroll
            for (int tm = 0; tm < 4; tm++) {
                uint32_t off = SWZ128((uint32_t)((wm + tm * 16 + rA) * 128 + cA + k16 * 32));
                LDSM_X4(ah[tm], sAh + off);
                if (TWO_PASS) LDSM_X4(al[tm], sAl + off);
            }
            #pragma unroll
            for (int p = 0; p < 4; p++) {
                uint32_t off = SWZ128((uint32_t)((wn + p * 16 + rB) * 128 + cB + k16 * 32));
                uint32_t t[4];
                LDSM_X4(t, sBh + off);
                bh[2*p][0] = t[0]; bh[2*p][1] = t[1];
                bh[2*p+1][0] = t[2]; bh[2*p+1][1] = t[3];
            }
            #pragma unroll
            for (int tm = 0; tm < 4; tm++)
                #pragma unroll
                for (int tn = 0; tn < 8; tn++) {
                    mma16816(acc[tm][tn], ah[tm], bh[tn]);
                    if (TWO_PASS) mma16816(acc[tm][tn], al[tm], bh[tn]);
                }
        }
        if (++sidx == NSTG) sidx = 0;
        __syncthreads();
    }

    const int lr4 = lane >> 2, lc2 = (lane & 3) << 1;
    #pragma unroll
    for (int tm = 0; tm < 4; tm++)
        #pragma unroll
        for (int tn = 0; tn < 8; tn++) {
            int gr = m0 + wm + tm * 16 + lr4;
            int gc = n0 + wn + tn * 8 + lc2;
            float sc = (gc < scale_cols) ? scale : 1.0f;
            float v0 = acc[tm][tn][0] * sc, v1 = acc[tm][tn][1] * sc;
            float v2 = acc[tm][tn][2] * sc, v3 = acc[tm][tn][3] * sc;
            if (OUT_HL) {
                bool lo = (gc >= lo_c0) && (gc < lo_c1);
                if (lo) {
                    write_hl2(Ch, Cl, (size_t)gr * N + gc, v0, v1);
                    write_hl2(Ch, Cl, (size_t)(gr + 8) * N + gc, v2, v3);
                } else {
                    write_h2(Ch, (size_t)gr * N + gc, v0, v1);
                    write_h2(Ch, (size_t)(gr + 8) * N + gc, v2, v3);
                }
            } else {
                float* c0 = C + (size_t)gr * N + gc;
                c0[0] = v0; c0[1] = v1;
                float* c1 = c0 + 8 * (size_t)N;
                c1[0] = v2; c1[1] = v3;
            }
        }
}

// ---------------- attn_sim (HMMA, 2-pass): sim = qh @ (kh+kl)^T, mask, relu^2 ----------------
#define ASTAGE_B (3*TILE_B)          // Qh, Kh, Kl
#define ASIM_SMEM (NSTG*ASTAGE_B + 1024)

__global__ __launch_bounds__(256, 1) void attn_sim_hmma(
    const __half* __restrict__ qkvh, const __half* __restrict__ qkvl,
    __half* __restrict__ awh)
{
    extern __shared__ char smem[];
    const uint32_t tiles = (smem_u32(smem) + 1023) & ~1023u;
    const int tid = threadIdx.x, wid = tid >> 5, lane = tid & 31;
    const int jhalf = blockIdx.x;
    const int blk = blockIdx.y;
    const int b = blk >> 6, wblk = blk & 63;
    const int qbase = b * TT + wblk * WSZ;
    const int krow0 = qbase - WSZ + jhalf * WSZ;
    const int bstart = b * TT;
    const int wm = (wid & 1) << 6, wn = (wid >> 1) << 5;

    float acc[4][4][4];
    #pragma unroll
    for (int a = 0; a < 4; a++)
        #pragma unroll
        for (int b2 = 0; b2 < 4; b2++)
            #pragma unroll
            for (int c = 0; c < 4; c++) acc[a][b2][c] = 0.f;

    const int mat = lane >> 3, lr = lane & 7;
    const int rA = ((mat & 1) << 3) + lr, cA = (mat >> 1) << 4;
    const int rB = ((mat >> 1) << 3) + lr, cB = (mat & 1) << 4;

    auto load_stage = [&](int st, int k0) {
        const uint32_t base = tiles + st * ASTAGE_B;
        #pragma unroll
        for (int i = 0; i < 4; i++) {
            int idx = tid + (i << 8);
            int row = idx >> 3, c = idx & 7;
            size_t qoff = (size_t)(qbase + row) * TDIM + k0 + c * 8;
            uint32_t d = SWZ128(row * 128 + c * 16);
            CPA(base + d, qkvh + qoff);
            int grow = krow0 + row;
            bool ok = grow >= bstart;
            size_t koff = (size_t)grow * TDIM + DIM + k0 + c * 8;
            CPA_Z(base + TILE_B + d, qkvh + koff, ok);
            CPA_Z(base + 2 * TILE_B + d, qkvl + koff, ok);
        }
    };

    const int NS = DIM >> 6;
    load_stage(0, 0);
    CP_COMMIT();
    load_stage(1, 64);
    CP_COMMIT();

    int sidx = 0;
    for (int s = 0; s < NS; s++) {
        CP_WAIT(1);
        __syncthreads();
        if (s + 2 < NS) {
            int nst = sidx + 2; if (nst >= NSTG) nst -= NSTG;
            load_stage(nst, (s + 2) * 64);
            CP_COMMIT();
        }
        const uint32_t sQh = tiles + sidx * ASTAGE_B;
        const uint32_t sKh = sQh + TILE_B;
        const uint32_t sKl = sQh + 2 * TILE_B;

        #pragma unroll
        for (int k16 = 0; k16 < 4; k16++) {
            uint32_t ah[4][4], bh[4][2], bl[4][2];
            #pragma unroll
            for (int tm = 0; tm < 4; tm++) {
                uint32_t off = SWZ128((uint32_t)((wm + tm * 16 + rA) * 128 + cA + k16 * 32));
                LDSM_X4(ah[tm], sQh + off);
            }
            #pragma unroll
            for (int p = 0; p < 2; p++) {
                uint32_t off = SWZ128((uint32_t)((wn + p * 16 + rB) * 128 + cB + k16 * 32));
                uint32_t t[4];
                LDSM_X4(t, sKh + off);
                bh[2*p][0] = t[0]; bh[2*p][1] = t[1];
                bh[2*p+1][0] = t[2]; bh[2*p+1][1] = t[3];
                LDSM_X4(t, sKl + off);
                bl[2*p][0] = t[0]; bl[2*p][1] = t[1];
                bl[2*p+1][0] = t[2]; bl[2*p+1][1] = t[3];
            }
            #pragma unroll
            for (int tm = 0; tm < 4; tm++)
                #pragma unroll
                for (int tn = 0; tn < 4; tn++) {
                    mma16816(acc[tm][tn], ah[tm], bh[tn]);
                    mma16816(acc[tm][tn], ah[tm], bl[tn]);
                }
        }
        if (++sidx == NSTG) sidx = 0;
        __syncthreads();
    }

    const bool prevok = (wblk > 0);
    const int lr4 = lane >> 2, lc2 = (lane & 3) << 1;
    __half* oh = awh + (size_t)blk * WSZ * 256;
    #pragma unroll
    for (int tm = 0; tm < 4; tm++)
        #pragma unroll
        for (int tn = 0; tn < 4; tn++) {
            #pragma unroll
            for (int half8 = 0; half8 < 2; half8++) {
                int i = wm + tm * 16 + lr4 + half8 * 8;
                int jl = wn + tn * 8 + lc2;
                int j = (jhalf << 7) + jl;
                float r[2];
                #pragma unroll
                for (int u = 0; u < 2; u++) {
                    int jj = j + u;
                    bool keep = (jj >= i) && (jj <= i + WSZ) && (prevok || jj >= WSZ);
                    float sv = acc[tm][tn][half8 * 2 + u];
                    r[u] = (keep && sv > 0.f) ? sv * sv : 0.f;
                }
                write_h2(oh, (size_t)i * 256 + j, r[0], r[1]);
            }
        }
}

// ---------------- attn_out (HMMA): out = attn @ v2, single-pass, hi-only ----------------
#define VTILE_B  16384
#define OSTAGE_B (TILE_B + VTILE_B)
#define AOUT_SMEM (NSTG*OSTAGE_B + 1024)
#define SWZV(off) ((off) ^ ((((off) >> 8) & 7) << 4))

__global__ __launch_bounds__(256, 1) void attn_out_hmma(
    const __half* __restrict__ qkvh, const __half* __restrict__ awh,
    __half* __restrict__ ath)
{
    extern __shared__ char smem[];
    const uint32_t tiles = (smem_u32(smem) + 1023) & ~1023u;
    const int tid = threadIdx.x, wid = tid >> 5, lane = tid & 31;
    const int n0 = blockIdx.x << 7;
    const int blk = blockIdx.y;
    const int b = blk >> 6, wblk = blk & 63;
    const int qbase = b * TT + wblk * WSZ;
    const int krow0 = qbase - WSZ;
    const int bstart = b * TT;
    const int wm = (wid & 1) << 6, wn = (wid >> 1) << 5;

    const __half* Ah = awh + (size_t)blk * WSZ * 256;

    float acc[4][4][4];
    #pragma unroll
    for (int a = 0; a < 4; a++)
        #pragma unroll
        for (int b2 = 0; b2 < 4; b2++)
            #pragma unroll
            for (int c = 0; c < 4; c++) acc[a][b2][c] = 0.f;

    const int mat = lane >> 3, lr = lane & 7;
    const int rA = ((mat & 1) << 3) + lr, cA = (mat >> 1) << 4;

    auto load_stage = [&](int st, int k0) {
        const uint32_t base = tiles + st * OSTAGE_B;
        #pragma unroll
        for (int i = 0; i < 4; i++) {
            int idx = tid + (i << 8);
            int row = idx >> 3, c = idx & 7;
            size_t off = (size_t)row * 256 + k0 + c * 8;
            CPA(base + SWZ128(row * 128 + c * 16), Ah + off);
        }
        #pragma unroll
        for (int i = 0; i < 4; i++) {
            int idx = tid + (i << 8);
            int j = idx >> 4, c = idx & 15;
            int grow = krow0 + k0 + j;
            bool ok = grow >= bstart;
            size_t off = (size_t)grow * TDIM + 2 * DIM + n0 + c * 8;
            CPA_Z(base + TILE_B + SWZV((uint32_t)(j * 256 + c * 16)), qkvh + off, ok);
        }
    };

    const int NS = 4;
    load_stage(0, 0);
    CP_COMMIT();
    load_stage(1, 64);
    CP_COMMIT();

    int sidx = 0;
    for (int s = 0; s < NS; s++) {
        CP_WAIT(1);
        __syncthreads();
        if (s + 2 < NS) {
            int nst = sidx + 2; if (nst >= NSTG) nst -= NSTG;
            load_stage(nst, (s + 2) * 64);
            CP_COMMIT();
        }
        const uint32_t sAh = tiles + sidx * OSTAGE_B;
        const uint32_t sVh = sAh + TILE_B;

        #pragma unroll
        for (int k16 = 0; k16 < 4; k16++) {
            uint32_t ah[4][4], bh[4][2];
            #pragma unroll
            for (int tm = 0; tm < 4; tm++) {
                uint32_t off = SWZ128((uint32_t)((wm + tm * 16 + rA) * 128 + cA + k16 * 32));
                LDSM_X4(ah[tm], sAh + off);
            }
            #pragma unroll
            for (int p = 0; p < 2; p++) {
                int nn = wn + p * 16;
                uint32_t off = SWZV((uint32_t)((k16 * 16 + (lane & 15)) * 256 + (nn + ((lane >> 4) << 3)) * 2));
                uint32_t t[4];
                LDSM_X4_T(t, sVh + off);
                bh[2*p][0] = t[0]; bh[2*p][1] = t[1];
                bh[2*p+1][0] = t[2]; bh[2*p+1][1] = t[3];
            }
            #pragma unroll
            for (int tm = 0; tm < 4; tm++)
                #pragma unroll
                for (int tn = 0; tn < 4; tn++)
                    mma16816(acc[tm][tn], ah[tm], bh[tn]);
        }
        if (++sidx == NSTG) sidx = 0;
        __syncthreads();
    }

    const int lr4 = lane >> 2, lc2 = (lane & 3) << 1;
    #pragma unroll
    for (int tm = 0; tm < 4; tm++)
        #pragma unroll
        for (int tn = 0; tn < 4; tn++) {
            int gr = qbase + wm + tm * 16 + lr4;
            int gc = n0 + wn + tn * 8 + lc2;
            write_h2(ath, (size_t)gr * DIM + gc, acc[tm][tn][0], acc[tm][tn][1]);
            write_h2(ath, (size_t)(gr + 8) * DIM + gc, acc[tm][tn][2], acc[tm][tn][3]);
        }
}

// ---------------------------------------------------------------------------
extern "C" void kernel_launch(void* const* d_in, const int* in_sizes, int n_in,
                              void* d_out, int out_size)
{
    (void)in_sizes; (void)n_in; (void)out_size;
    const float* x      = (const float*)d_in[0];
    const float* w_attn = (const float*)d_in[1];
    const float* w_o    = (const float*)d_in[2];
    float* out = (float*)d_out;

    __half *xh, *wah, *woh, *qkvh, *qkvl, *awh, *ath;
    cudaGetSymbolAddress((void**)&xh,   g_xh);
    cudaGetSymbolAddress((void**)&wah,  g_wah);  cudaGetSymbolAddress((void**)&woh,  g_woh);
    cudaGetSymbolAddress((void**)&qkvh, g_qkvh); cudaGetSymbolAddress((void**)&qkvl, g_qkvl);
    cudaGetSymbolAddress((void**)&awh,  g_awh);
    cudaGetSymbolAddress((void**)&ath,  g_ath);

    cudaFuncSetAttribute((const void*)gemm_hmma<1,0>, cudaFuncAttributeMaxDynamicSharedMemorySize, GEMM_SMEM);
    cudaFuncSetAttribute((const void*)gemm_hmma<0,0>, cudaFuncAttributeMaxDynamicSharedMemorySize, GEMM_SMEM);
    cudaFuncSetAttribute((const void*)attn_sim_hmma, cudaFuncAttributeMaxDynamicSharedMemorySize, ASIM_SMEM);
    cudaFuncSetAttribute((const void*)attn_out_hmma, cudaFuncAttributeMaxDynamicSharedMemorySize, AOUT_SMEM);

    // 0) fp16 splits (hi only everywhere)
    {
        int n4 = MROWS * DIM / 4;
        split_h_kernel<<<(n4 + 255) / 256, 256>>>(x, xh, n4);
        n4 = TDIM * DIM / 4;
        split_h_kernel<<<(n4 + 255) / 256, 256>>>(w_attn, wah, n4);
        n4 = DIM * DIM / 4;
        split_h_kernel<<<(n4 + 255) / 256, 256>>>(w_o, woh, n4);
    }

    // 1) qkv = xh @ wah^T -> hi fp16 everywhere, lo only for k cols [2048,4096)
    gemm_hmma<1,0><<<dim3(TDIM / 256, MROWS / 128), 256, GEMM_SMEM>>>(
        xh, xh, wah, nullptr, qkvh, qkvl, MROWS, TDIM, DIM, DIM, 1.0f / (float)WSZ,
        DIM, 2 * DIM);

    // 2) attention weights (2-pass HMMA: qh·kh + qh·kl) -> hi-only fp16
    attn_sim_hmma<<<dim3(2, NBLK), 256, ASIM_SMEM>>>(qkvh, qkvl, awh);

    // 3) attn @ v (single-pass HMMA) -> hi-only fp16
    attn_out_hmma<<<dim3(DIM / 128, NBLK), 256, AOUT_SMEM>>>(qkvh, awh, ath);

    // 4) out = att @ w_o^T -> fp32  [single-pass]
    gemm_hmma<0,0><<<dim3(DIM / 256, MROWS / 128), 256, GEMM_SMEM>>>(
        ath, ath, woh, out, nullptr, nullptr, MROWS, DIM, DIM, 0, 1.0f, 0, 0);
}

// round 13
// speedup vs baseline: 1.9255x; 1.0137x over previous
#include <cuda_runtime.h>
#include <cuda_fp16.h>
#include <cstdint>
#include <cstddef>

#define DIM   2048
#define TDIM  6144
#define BB    2
#define TT    8192
#define MROWS (BB*TT)
#define WSZ   128
#define NBLK  (MROWS/WSZ)

// ---------------- scratch (static device globals) ----------------
__device__ __half g_xh[(size_t)MROWS * DIM];
__device__ __half g_wah[(size_t)TDIM * DIM];
__device__ __half g_woh[(size_t)DIM * DIM];
__device__ __half g_qkvh[(size_t)MROWS * TDIM];
__device__ __half g_qkvl[(size_t)MROWS * TDIM];   // only k-region cols [2048,4096) valid
__device__ __half g_awh[(size_t)NBLK * WSZ * 256];
__device__ __half g_ath[(size_t)MROWS * DIM];

// ---------------- helpers ----------------
__device__ __forceinline__ uint32_t smem_u32(const void* p) {
    uint32_t a;
    asm("{ .reg .u64 t; cvta.to.shared.u64 t, %1; cvt.u32.u64 %0, t; }" : "=r"(a) : "l"(p));
    return a;
}
#define SWZ128(o) ((o) ^ (((o) >> 3) & 0x70))
#define SWZV(off) ((off) ^ ((((off) >> 8) & 7) << 4))   // 256B-row swizzle

#define LDSM_X4(r, a) \
    asm volatile("ldmatrix.sync.aligned.m8n8.x4.shared.b16 {%0,%1,%2,%3}, [%4];" \
        : "=r"((r)[0]), "=r"((r)[1]), "=r"((r)[2]), "=r"((r)[3]) : "r"(a))
#define LDSM_X4_T(r, a) \
    asm volatile("ldmatrix.sync.aligned.m8n8.x4.trans.shared.b16 {%0,%1,%2,%3}, [%4];" \
        : "=r"((r)[0]), "=r"((r)[1]), "=r"((r)[2]), "=r"((r)[3]) : "r"(a))

__device__ __forceinline__ void mma16816(float* d, const uint32_t* a, const uint32_t* b) {
    asm volatile("mma.sync.aligned.m16n8k16.row.col.f32.f16.f16.f32 "
        "{%0,%1,%2,%3}, {%4,%5,%6,%7}, {%8,%9}, {%0,%1,%2,%3};"
        : "+f"(d[0]), "+f"(d[1]), "+f"(d[2]), "+f"(d[3])
        : "r"(a[0]), "r"(a[1]), "r"(a[2]), "r"(a[3]), "r"(b[0]), "r"(b[1]));
}

#define CPA(dst, src) \
    asm volatile("cp.async.cg.shared.global [%0], [%1], 16;" :: "r"(dst), "l"(src))
#define CPA_Z(dst, src, pred) \
    asm volatile("cp.async.cg.shared.global [%0], [%1], 16, %2;" :: "r"(dst), "l"(src), "r"((pred) ? 16 : 0))
#define CP_COMMIT() asm volatile("cp.async.commit_group;" ::: "memory")
#define CP_WAIT(n)  asm volatile("cp.async.wait_group %0;" :: "n"(n) : "memory")

__device__ __forceinline__ void write_hl2(__half* H, __half* L, size_t idx, float v0, float v1) {
    __half h0 = __float2half_rn(v0), h1 = __float2half_rn(v1);
    __half l0 = __float2half_rn(v0 - __half2float(h0));
    __half l1 = __float2half_rn(v1 - __half2float(h1));
    *(__half2*)(H + idx) = __halves2half2(h0, h1);
    *(__half2*)(L + idx) = __halves2half2(l0, l1);
}
__device__ __forceinline__ void write_h2(__half* H, size_t idx, float v0, float v1) {
    *(__half2*)(H + idx) = __halves2half2(__float2half_rn(v0), __float2half_rn(v1));
}

// ---------------- fp32 -> fp16 split (hi only) ----------------
__global__ __launch_bounds__(256) void split_h_kernel(
    const float* __restrict__ src, __half* __restrict__ hi, int n4)
{
    int i = blockIdx.x * blockDim.x + threadIdx.x;
    if (i >= n4) return;
    float4 v = ((const float4*)src)[i];
    float vv[4] = {v.x, v.y, v.z, v.w};
    __half h4[4];
    #pragma unroll
    for (int j = 0; j < 4; j++) h4[j] = __float2half_rn(vv[j]);
    ((uint2*)hi)[i] = *(uint2*)h4;
}

// ---------------- single-pass fp16 HMMA GEMM: C = A @ B^T ----------------
// 128x256 CTA tile, 256 threads / 8 warps, warp tile 64x64.
// K-chunk 128 (256B rows, SWZV swizzle), 2-stage ping-pong, ONE sync/stage.
// OUT_HL=1: write hi everywhere, lo only for cols in [lo_c0, lo_c1).
#define GA_TILE  32768               // 128 rows x 256 bytes
#define GB_TILE  65536               // 256 rows x 256 bytes
#define GSTAGE   (GA_TILE + GB_TILE) // 96 KB
#define GEMM_SMEM (2*GSTAGE + 1024)

template<int OUT_HL>
__global__ __launch_bounds__(256, 1) void gemm_hmma(
    const __half* __restrict__ Ahg, const __half* __restrict__ Bhg,
    float* __restrict__ C, __half* __restrict__ Ch, __half* __restrict__ Cl,
    int M, int N, int K, int scale_cols, float scale, int lo_c0, int lo_c1)
{
    extern __shared__ char smem[];
    const uint32_t tiles = (smem_u32(smem) + 1023) & ~1023u;
    const int tid = threadIdx.x, wid = tid >> 5, lane = tid & 31;
    const int m0 = blockIdx.y << 7, n0 = blockIdx.x << 8;
    const int wm = (wid & 1) << 6, wn = (wid >> 1) << 6;

    const __half* Ah = Ahg + (size_t)m0 * K;
    const __half* Bh = Bhg + (size_t)n0 * K;

    float acc[4][8][4];
    #pragma unroll
    for (int a = 0; a < 4; a++)
        #pragma unroll
        for (int b = 0; b < 8; b++)
            #pragma unroll
            for (int c = 0; c < 4; c++) acc[a][b][c] = 0.f;

    const int mat = lane >> 3, lr = lane & 7;
    const int rA = ((mat & 1) << 3) + lr, cA = (mat >> 1) << 4;
    const int rB = ((mat >> 1) << 3) + lr, cB = (mat & 1) << 4;

    auto load_stage = [&](int st, int k0) {
        const uint32_t base = tiles + st * GSTAGE;
        // A: 128 rows x 256B  (2048 chunks of 16B)
        #pragma unroll
        for (int i = 0; i < 8; i++) {
            int idx = tid + (i << 8);
            int row = idx >> 4, c = idx & 15;
            CPA(base + SWZV((uint32_t)(row * 256 + c * 16)),
                Ah + (size_t)row * K + k0 + c * 8);
        }
        // B: 256 rows x 256B  (4096 chunks)
        #pragma unroll
        for (int i = 0; i < 16; i++) {
            int idx = tid + (i << 8);
            int row = idx >> 4, c = idx & 15;
            CPA(base + GA_TILE + SWZV((uint32_t)(row * 256 + c * 16)),
                Bh + (size_t)row * K + k0 + c * 8);
        }
    };

    const int NS = K >> 7;            // K-chunk 128
    load_stage(0, 0);
    CP_COMMIT();

    for (int s = 0; s < NS; s++) {
        CP_WAIT(0);
        __syncthreads();              // buffer s ready; all warps done with buffer s-1
        if (s + 1 < NS) {
            load_stage((s + 1) & 1, (s + 1) * 128);
            CP_COMMIT();
        }
        const uint32_t sAh = tiles + (s & 1) * GSTAGE;
        const uint32_t sBh = sAh + GA_TILE;

        #pragma unroll
        for (int k16 = 0; k16 < 8; k16++) {
            uint32_t ah[4][4], bh[8][2];
            #pragma unroll
            for (int tm = 0; tm < 4; tm++) {
                uint32_t off = SWZV((uint32_t)((wm + tm * 16 + rA) * 256 + cA + k16 * 32));
                LDSM_X4(ah[tm], sAh + off);
            }
            #pragma unroll
            for (int p = 0; p < 4; p++) {
                uint32_t off = SWZV((uint32_t)((wn + p * 16 + rB) * 256 + cB + k16 * 32));
                uint32_t t[4];
                LDSM_X4(t, sBh + off);
                bh[2*p][0] = t[0]; bh[2*p][1] = t[1];
                bh[2*p+1][0] = t[2]; bh[2*p+1][1] = t[3];
            }
            #pragma unroll
            for (int tm = 0; tm < 4; tm++)
                #pragma unroll
                for (int tn = 0; tn < 8; tn++)
                    mma16816(acc[tm][tn], ah[tm], bh[tn]);
        }
    }

    const int lr4 = lane >> 2, lc2 = (lane & 3) << 1;
    #pragma unroll
    for (int tm = 0; tm < 4; tm++)
        #pragma unroll
        for (int tn = 0; tn < 8; tn++) {
            int gr = m0 + wm + tm * 16 + lr4;
            int gc = n0 + wn + tn * 8 + lc2;
            float sc = (gc < scale_cols) ? scale : 1.0f;
            float v0 = acc[tm][tn][0] * sc, v1 = acc[tm][tn][1] * sc;
            float v2 = acc[tm][tn][2] * sc, v3 = acc[tm][tn][3] * sc;
            if (OUT_HL) {
                bool lo = (gc >= lo_c0) && (gc < lo_c1);
                if (lo) {
                    write_hl2(Ch, Cl, (size_t)gr * N + gc, v0, v1);
                    write_hl2(Ch, Cl, (size_t)(gr + 8) * N + gc, v2, v3);
                } else {
                    write_h2(Ch, (size_t)gr * N + gc, v0, v1);
                    write_h2(Ch, (size_t)(gr + 8) * N + gc, v2, v3);
                }
            } else {
                float* c0 = C + (size_t)gr * N + gc;
                c0[0] = v0; c0[1] = v1;
                float* c1 = c0 + 8 * (size_t)N;
                c1[0] = v2; c1[1] = v3;
            }
        }
}

// ---------------- attn_sim (HMMA, 2-pass): sim = qh @ (kh+kl)^T, mask, relu^2 ----------------
#define TILE_B   16384
#define NSTG     3
#define ASTAGE_B (3*TILE_B)          // Qh, Kh, Kl
#define ASIM_SMEM (NSTG*ASTAGE_B + 1024)

__global__ __launch_bounds__(256, 1) void attn_sim_hmma(
    const __half* __restrict__ qkvh, const __half* __restrict__ qkvl,
    __half* __restrict__ awh)
{
    extern __shared__ char smem[];
    const uint32_t tiles = (smem_u32(smem) + 1023) & ~1023u;
    const int tid = threadIdx.x, wid = tid >> 5, lane = tid & 31;
    const int jhalf = blockIdx.x;
    const int blk = blockIdx.y;
    const int b = blk >> 6, wblk = blk & 63;
    const int qbase = b * TT + wblk * WSZ;
    const int krow0 = qbase - WSZ + jhalf * WSZ;
    const int bstart = b * TT;
    const int wm = (wid & 1) << 6, wn = (wid >> 1) << 5;

    float acc[4][4][4];
    #pragma unroll
    for (int a = 0; a < 4; a++)
        #pragma unroll
        for (int b2 = 0; b2 < 4; b2++)
            #pragma unroll
            for (int c = 0; c < 4; c++) acc[a][b2][c] = 0.f;

    const int mat = lane >> 3, lr = lane & 7;
    const int rA = ((mat & 1) << 3) + lr, cA = (mat >> 1) << 4;
    const int rB = ((mat >> 1) << 3) + lr, cB = (mat & 1) << 4;

    auto load_stage = [&](int st, int k0) {
        const uint32_t base = tiles + st * ASTAGE_B;
        #pragma unroll
        for (int i = 0; i < 4; i++) {
            int idx = tid + (i << 8);
            int row = idx >> 3, c = idx & 7;
            size_t qoff = (size_t)(qbase + row) * TDIM + k0 + c * 8;
            uint32_t d = SWZ128(row * 128 + c * 16);
            CPA(base + d, qkvh + qoff);
            int grow = krow0 + row;
            bool ok = grow >= bstart;
            size_t koff = (size_t)grow * TDIM + DIM + k0 + c * 8;
            CPA_Z(base + TILE_B + d, qkvh + koff, ok);
            CPA_Z(base + 2 * TILE_B + d, qkvl + koff, ok);
        }
    };

    const int NS = DIM >> 6;
    load_stage(0, 0);
    CP_COMMIT();
    load_stage(1, 64);
    CP_COMMIT();

    int sidx = 0;
    for (int s = 0; s < NS; s++) {
        CP_WAIT(1);
        __syncthreads();
        if (s + 2 < NS) {
            int nst = sidx + 2; if (nst >= NSTG) nst -= NSTG;
            load_stage(nst, (s + 2) * 64);
            CP_COMMIT();
        }
        const uint32_t sQh = tiles + sidx * ASTAGE_B;
        const uint32_t sKh = sQh + TILE_B;
        const uint32_t sKl = sQh + 2 * TILE_B;

        #pragma unroll
        for (int k16 = 0; k16 < 4; k16++) {
            uint32_t ah[4][4], bh[4][2], bl[4][2];
            #pragma unroll
            for (int tm = 0; tm < 4; tm++) {
                uint32_t off = SWZ128((uint32_t)((wm + tm * 16 + rA) * 128 + cA + k16 * 32));
                LDSM_X4(ah[tm], sQh + off);
            }
            #pragma unroll
            for (int p = 0; p < 2; p++) {
                uint32_t off = SWZ128((uint32_t)((wn + p * 16 + rB) * 128 + cB + k16 * 32));
                uint32_t t[4];
                LDSM_X4(t, sKh + off);
                bh[2*p][0] = t[0]; bh[2*p][1] = t[1];
                bh[2*p+1][0] = t[2]; bh[2*p+1][1] = t[3];
                LDSM_X4(t, sKl + off);
                bl[2*p][0] = t[0]; bl[2*p][1] = t[1];
                bl[2*p+1][0] = t[2]; bl[2*p+1][1] = t[3];
            }
            #pragma unroll
            for (int tm = 0; tm < 4; tm++)
                #pragma unroll
                for (int tn = 0; tn < 4; tn++) {
                    mma16816(acc[tm][tn], ah[tm], bh[tn]);
                    mma16816(acc[tm][tn], ah[tm], bl[tn]);
                }
        }
        if (++sidx == NSTG) sidx = 0;
        __syncthreads();
    }

    const bool prevok = (wblk > 0);
    const int lr4 = lane >> 2, lc2 = (lane & 3) << 1;
    __half* oh = awh + (size_t)blk * WSZ * 256;
    #pragma unroll
    for (int tm = 0; tm < 4; tm++)
        #pragma unroll
        for (int tn = 0; tn < 4; tn++) {
            #pragma unroll
            for (int half8 = 0; half8 < 2; half8++) {
                int i = wm + tm * 16 + lr4 + half8 * 8;
                int jl = wn + tn * 8 + lc2;
                int j = (jhalf << 7) + jl;
                float r[2];
                #pragma unroll
                for (int u = 0; u < 2; u++) {
                    int jj = j + u;
                    bool keep = (jj >= i) && (jj <= i + WSZ) && (prevok || jj >= WSZ);
                    float sv = acc[tm][tn][half8 * 2 + u];
                    r[u] = (keep && sv > 0.f) ? sv * sv : 0.f;
                }
                write_h2(oh, (size_t)i * 256 + j, r[0], r[1]);
            }
        }
}

// ---------------- attn_out (HMMA): out = attn @ v2, single-pass, hi-only ----------------
#define VTILE_B  16384
#define OSTAGE_B (TILE_B + VTILE_B)
#define AOUT_SMEM (NSTG*OSTAGE_B + 1024)

__global__ __launch_bounds__(256, 1) void attn_out_hmma(
    const __half* __restrict__ qkvh, const __half* __restrict__ awh,
    __half* __restrict__ ath)
{
    extern __shared__ char smem[];
    const uint32_t tiles = (smem_u32(smem) + 1023) & ~1023u;
    const int tid = threadIdx.x, wid = tid >> 5, lane = tid & 31;
    const int n0 = blockIdx.x << 7;
    const int blk = blockIdx.y;
    const int b = blk >> 6, wblk = blk & 63;
    const int qbase = b * TT + wblk * WSZ;
    const int krow0 = qbase - WSZ;
    const int bstart = b * TT;
    const int wm = (wid & 1) << 6, wn = (wid >> 1) << 5;

    const __half* Ah = awh + (size_t)blk * WSZ * 256;

    float acc[4][4][4];
    #pragma unroll
    for (int a = 0; a < 4; a++)
        #pragma unroll
        for (int b2 = 0; b2 < 4; b2++)
            #pragma unroll
            for (int c = 0; c < 4; c++) acc[a][b2][c] = 0.f;

    const int mat = lane >> 3, lr = lane & 7;
    const int rA = ((mat & 1) << 3) + lr, cA = (mat >> 1) << 4;

    auto load_stage = [&](int st, int k0) {
        const uint32_t base = tiles + st * OSTAGE_B;
        #pragma unroll
        for (int i = 0; i < 4; i++) {
            int idx = tid + (i << 8);
            int row = idx >> 3, c = idx & 7;
            size_t off = (size_t)row * 256 + k0 + c * 8;
            CPA(base + SWZ128(row * 128 + c * 16), Ah + off);
        }
        #pragma unroll
        for (int i = 0; i < 4; i++) {
            int idx = tid + (i << 8);
            int j = idx >> 4, c = idx & 15;
            int grow = krow0 + k0 + j;
            bool ok = grow >= bstart;
            size_t off = (size_t)grow * TDIM + 2 * DIM + n0 + c * 8;
            CPA_Z(base + TILE_B + SWZV((uint32_t)(j * 256 + c * 16)), qkvh + off, ok);
        }
    };

    const int NS = 4;
    load_stage(0, 0);
    CP_COMMIT();
    load_stage(1, 64);
    CP_COMMIT();

    int sidx = 0;
    for (int s = 0; s < NS; s++) {
        CP_WAIT(1);
        __syncthreads();
        if (s + 2 < NS) {
            int nst = sidx + 2; if (nst >= NSTG) nst -= NSTG;
            load_stage(nst, (s + 2) * 64);
            CP_COMMIT();
        }
        const uint32_t sAh = tiles + sidx * OSTAGE_B;
        const uint32_t sVh = sAh + TILE_B;

        #pragma unroll
        for (int k16 = 0; k16 < 4; k16++) {
            uint32_t ah[4][4], bh[4][2];
            #pragma unroll
            for (int tm = 0; tm < 4; tm++) {
                uint32_t off = SWZ128((uint32_t)((wm + tm * 16 + rA) * 128 + cA + k16 * 32));
                LDSM_X4(ah[tm], sAh + off);
            }
            #pragma unroll
            for (int p = 0; p < 2; p++) {
                int nn = wn + p * 16;
                uint32_t off = SWZV((uint32_t)((k16 * 16 + (lane & 15)) * 256 + (nn + ((lane >> 4) << 3)) * 2));
                uint32_t t[4];
                LDSM_X4_T(t, sVh + off);
                bh[2*p][0] = t[0]; bh[2*p][1] = t[1];
                bh[2*p+1][0] = t[2]; bh[2*p+1][1] = t[3];
            }
            #pragma unroll
            for (int tm = 0; tm < 4; tm++)
                #pragma unroll
                for (int tn = 0; tn < 4; tn++)
                    mma16816(acc[tm][tn], ah[tm], bh[tn]);
        }
        if (++sidx == NSTG) sidx = 0;
        __syncthreads();
    }

    const int lr4 = lane >> 2, lc2 = (lane & 3) << 1;
    #pragma unroll
    for (int tm = 0; tm < 4; tm++)
        #pragma unroll
        for (int tn = 0; tn < 4; tn++) {
            int gr = qbase + wm + tm * 16 + lr4;
            int gc = n0 + wn + tn * 8 + lc2;
            write_h2(ath, (size_t)gr * DIM + gc, acc[tm][tn][0], acc[tm][tn][1]);
            write_h2(ath, (size_t)(gr + 8) * DIM + gc, acc[tm][tn][2], acc[tm][tn][3]);
        }
}

// ---------------------------------------------------------------------------
extern "C" void kernel_launch(void* const* d_in, const int* in_sizes, int n_in,
                              void* d_out, int out_size)
{
    (void)in_sizes; (void)n_in; (void)out_size;
    const float* x      = (const float*)d_in[0];
    const float* w_attn = (const float*)d_in[1];
    const float* w_o    = (const float*)d_in[2];
    float* out = (float*)d_out;

    __half *xh, *wah, *woh, *qkvh, *qkvl, *awh, *ath;
    cudaGetSymbolAddress((void**)&xh,   g_xh);
    cudaGetSymbolAddress((void**)&wah,  g_wah);  cudaGetSymbolAddress((void**)&woh,  g_woh);
    cudaGetSymbolAddress((void**)&qkvh, g_qkvh); cudaGetSymbolAddress((void**)&qkvl, g_qkvl);
    cudaGetSymbolAddress((void**)&awh,  g_awh);
    cudaGetSymbolAddress((void**)&ath,  g_ath);

    cudaFuncSetAttribute((const void*)gemm_hmma<1>, cudaFuncAttributeMaxDynamicSharedMemorySize, GEMM_SMEM);
    cudaFuncSetAttribute((const void*)gemm_hmma<0>, cudaFuncAttributeMaxDynamicSharedMemorySize, GEMM_SMEM);
    cudaFuncSetAttribute((const void*)attn_sim_hmma, cudaFuncAttributeMaxDynamicSharedMemorySize, ASIM_SMEM);
    cudaFuncSetAttribute((const void*)attn_out_hmma, cudaFuncAttributeMaxDynamicSharedMemorySize, AOUT_SMEM);

    // 0) fp16 splits (hi only everywhere)
    {
        int n4 = MROWS * DIM / 4;
        split_h_kernel<<<(n4 + 255) / 256, 256>>>(x, xh, n4);
        n4 = TDIM * DIM / 4;
        split_h_kernel<<<(n4 + 255) / 256, 256>>>(w_attn, wah, n4);
        n4 = DIM * DIM / 4;
        split_h_kernel<<<(n4 + 255) / 256, 256>>>(w_o, woh, n4);
    }

    // 1) qkv = xh @ wah^T -> hi fp16 everywhere, lo only for k cols [2048,4096)
    gemm_hmma<1><<<dim3(TDIM / 256, MROWS / 128), 256, GEMM_SMEM>>>(
        xh, wah, nullptr, qkvh, qkvl, MROWS, TDIM, DIM, DIM, 1.0f / (float)WSZ,
        DIM, 2 * DIM);

    // 2) attention weights (2-pass HMMA: qh·kh + qh·kl) -> hi-only fp16
    attn_sim_hmma<<<dim3(2, NBLK), 256, ASIM_SMEM>>>(qkvh, qkvl, awh);

    // 3) attn @ v (single-pass HMMA) -> hi-only fp16
    attn_out_hmma<<<dim3(DIM / 128, NBLK), 256, AOUT_SMEM>>>(qkvh, awh, ath);

    // 4) out = att @ w_o^T -> fp32  [single-pass]
    gemm_hmma<0><<<dim3(DIM / 256, MROWS / 128), 256, GEMM_SMEM>>>(
        ath, woh, out, nullptr, nullptr, MROWS, DIM, DIM, 0, 1.0f, 0, 0);
}